// round 10
// baseline (speedup 1.0000x reference)
#include <cuda_runtime.h>
#include <cuda_fp16.h>
#include <cstdint>

#define BQ    8192
#define FD    1024
#define HH    16
#define DD    64
#define SS    5
#define LW    3
#define CC    1000
#define GD    512
#define CSUM  1984   // 64+128+256+512+1024

// ---------------------------------------------------------------------------
// Scratch
// ---------------------------------------------------------------------------
__device__ __half g_MKh[FD * CSUM];
__device__ __half g_MVh[FD * CSUM];
__device__ __half g_sfh[(size_t)BQ * CSUM];
__device__ __half g_feath[(size_t)BQ * FD];
__device__ __half g_Wqh[FD * FD];
__device__ __half g_Wg1h[GD * FD];
__device__ float g_fbk[SS * FD];
__device__ float g_fbv[SS * FD];
__device__ __half g_Kh[(size_t)BQ * SS * FD];
__device__ __half g_Vh[(size_t)BQ * SS * FD];
__device__ float g_Q[(size_t)BQ * FD];
__device__ float g_H[(size_t)BQ * GD];
__device__ float g_si[BQ * SS];
__device__ float g_aw[BQ * SS];

// ---------------------------------------------------------------------------
// Helpers
// ---------------------------------------------------------------------------
__device__ __forceinline__ unsigned f2tf(float x) {
    unsigned r;
    asm("cvt.rna.tf32.f32 %0, %1;" : "=r"(r) : "f"(x));
    return r;
}
__device__ __forceinline__ float wredsum(float v) {
    #pragma unroll
    for (int o = 16; o; o >>= 1) v += __shfl_xor_sync(0xffffffffu, v, o);
    return v;
}
__device__ __forceinline__ void cp16(void* s, const void* g) {
    uint32_t sa = (uint32_t)__cvta_generic_to_shared(s);
    asm volatile("cp.async.cg.shared.global [%0], [%1], 16;\n" :: "r"(sa), "l"(g));
}
__device__ __forceinline__ void ldm_x4(unsigned& r0, unsigned& r1, unsigned& r2, unsigned& r3,
                                       uint32_t addr) {
    asm volatile("ldmatrix.sync.aligned.m8n8.x4.shared.b16 {%0,%1,%2,%3}, [%4];"
                 : "=r"(r0), "=r"(r1), "=r"(r2), "=r"(r3) : "r"(addr));
}

// ---------------------------------------------------------------------------
// f32 -> f16 conversion (8 segments, grid-stride)
// ---------------------------------------------------------------------------
struct ConvSeg { const float* src; __half* dst; int n4; };
struct ConvParams { ConvSeg seg[8]; };

__global__ void __launch_bounds__(256) convert_kernel(ConvParams p)
{
    const int stride = gridDim.x * blockDim.x;
    const int t0 = blockIdx.x * blockDim.x + threadIdx.x;
    #pragma unroll
    for (int s = 0; s < 8; s++) {
        const float* src = p.seg[s].src;
        __half* dst = p.seg[s].dst;
        const int n4 = p.seg[s].n4;
        for (int i = t0; i < n4; i += stride) {
            const float4 v = ((const float4*)src)[i];
            ((__half2*)dst)[2 * i + 0] = __floats2half2_rn(v.x, v.y);
            ((__half2*)dst)[2 * i + 1] = __floats2half2_rn(v.z, v.w);
        }
    }
}

// ---------------------------------------------------------------------------
// Batched NN GEMM (prep, tf32 mma.sync): writes half MK/MV
// ---------------------------------------------------------------------------
struct PrepSeg {
    const float* A;
    const float* B;
    __half*      C;
    int lda, ldb, ldc, K, xStart;
};
struct PrepParams { PrepSeg seg[10]; };

__global__ void __launch_bounds__(256) gemm_nn_prep(PrepParams p)
{
    __shared__ float As[128 * 36];
    __shared__ float Bs[64 * 36];

    const int bx = blockIdx.x;
    int si = 0;
    #pragma unroll
    for (int i = 1; i < 10; i++)
        if (bx >= p.seg[i].xStart) si = i;
    const PrepSeg d = p.seg[si];

    const int bn = (bx - d.xStart) * 64;
    const int bm = blockIdx.y * 128;
    const int tid  = threadIdx.x;
    const int warp = tid >> 5, lane = tid & 31;
    const int wm = (warp & 3) * 32;
    const int wn = (warp >> 2) * 32;
    const int g = lane >> 2, t = lane & 3;
    const int arow = tid >> 3;
    const int acol = (tid & 7) * 4;

    float acc[2][4][4];
    #pragma unroll
    for (int i = 0; i < 2; i++)
        #pragma unroll
        for (int j = 0; j < 4; j++)
            #pragma unroll
            for (int r = 0; r < 4; r++) acc[i][j][r] = 0.f;

    for (int kt = 0; kt < d.K; kt += 32) {
        #pragma unroll
        for (int r = 0; r < 4; r++) {
            const float4 v = *(const float4*)(d.A + (size_t)(bm + arow + 32 * r) * d.lda + kt + acol);
            float4 w;
            w.x = __uint_as_float(f2tf(v.x));
            w.y = __uint_as_float(f2tf(v.y));
            w.z = __uint_as_float(f2tf(v.z));
            w.w = __uint_as_float(f2tf(v.w));
            *(float4*)(&As[(arow + 32 * r) * 36 + acol]) = w;
        }
        #pragma unroll
        for (int r = 0; r < 2; r++) {
            const int kk = (tid >> 4) + 16 * r;
            const int nn = (tid & 15) * 4;
            const float4 v = *(const float4*)(d.B + (size_t)(kt + kk) * d.ldb + bn + nn);
            Bs[(nn + 0) * 36 + kk] = __uint_as_float(f2tf(v.x));
            Bs[(nn + 1) * 36 + kk] = __uint_as_float(f2tf(v.y));
            Bs[(nn + 2) * 36 + kk] = __uint_as_float(f2tf(v.z));
            Bs[(nn + 3) * 36 + kk] = __uint_as_float(f2tf(v.w));
        }
        __syncthreads();

        #pragma unroll
        for (int ks = 0; ks < 4; ks++) {
            const int k0 = ks * 8;
            unsigned af[2][4], bf[4][2];
            #pragma unroll
            for (int i = 0; i < 2; i++) {
                const int r0 = wm + i * 16;
                af[i][0] = __float_as_uint(As[(r0 + g    ) * 36 + k0 + t]);
                af[i][1] = __float_as_uint(As[(r0 + 8 + g) * 36 + k0 + t]);
                af[i][2] = __float_as_uint(As[(r0 + g    ) * 36 + k0 + t + 4]);
                af[i][3] = __float_as_uint(As[(r0 + 8 + g) * 36 + k0 + t + 4]);
            }
            #pragma unroll
            for (int j = 0; j < 4; j++) {
                const int c0 = wn + j * 8;
                bf[j][0] = __float_as_uint(Bs[(c0 + g) * 36 + k0 + t]);
                bf[j][1] = __float_as_uint(Bs[(c0 + g) * 36 + k0 + t + 4]);
            }
            #pragma unroll
            for (int i = 0; i < 2; i++)
                #pragma unroll
                for (int j = 0; j < 4; j++)
                    asm volatile(
                        "mma.sync.aligned.m16n8k8.row.col.f32.tf32.tf32.f32 "
                        "{%0,%1,%2,%3},{%4,%5,%6,%7},{%8,%9},{%0,%1,%2,%3};\n"
                        : "+f"(acc[i][j][0]), "+f"(acc[i][j][1]),
                          "+f"(acc[i][j][2]), "+f"(acc[i][j][3])
                        : "r"(af[i][0]), "r"(af[i][1]), "r"(af[i][2]), "r"(af[i][3]),
                          "r"(bf[j][0]), "r"(bf[j][1]));
        }
        __syncthreads();
    }

    #pragma unroll
    for (int i = 0; i < 2; i++) {
        #pragma unroll
        for (int j = 0; j < 4; j++) {
            const int row = bm + wm + i * 16 + g;
            const int col = bn + wn + j * 8 + t * 2;
            *(__half2*)(d.C + (size_t)row * d.ldc + col) =
                __floats2half2_rn(acc[i][j][0], acc[i][j][1]);
            *(__half2*)(d.C + (size_t)(row + 8) * d.ldc + col) =
                __floats2half2_rn(acc[i][j][2], acc[i][j][3]);
        }
    }
}

// ---------------------------------------------------------------------------
// Batched TN GEMM, fp16 m16n8k16 + ldmatrix.x4, fp32 accum.
// 3-stage cp.async pipeline, ONE __syncthreads per tile. 2 CTAs/SM.
// smem = 3*(128+128)*72 halves = 110592 B.
// ---------------------------------------------------------------------------
struct SegH {
    const __half* A;
    const __half* B;
    const float*  bias;
    float*        C;
    __half*       Ch;
    int lda, ldb, ldc, K, xStart;
};
struct SegHParams { SegH seg[12]; };

#define HT_ROWS 128
#define HT_LDS  72
#define HT_TILE (HT_ROWS * HT_LDS)
#define N_STAGE 3

__global__ void __launch_bounds__(256, 2) gemm_tn_f16(SegHParams p)
{
    extern __shared__ __half smemH[];
    __half* Asb = smemH;                        // N_STAGE * HT_TILE
    __half* Bsb = smemH + N_STAGE * HT_TILE;    // N_STAGE * HT_TILE

    const int bx = blockIdx.x;
    int si = 0;
    #pragma unroll
    for (int i = 1; i < 12; i++)
        if (bx >= p.seg[i].xStart) si = i;
    const SegH d = p.seg[si];

    const int bn = (bx - d.xStart) * 128;
    const int bm = blockIdx.y * 128;
    const int tid  = threadIdx.x;
    const int warp = tid >> 5, lane = tid & 31;
    const int wm = (warp & 1) * 64;
    const int wn = (warp >> 1) * 32;
    const int g = lane >> 2, t = lane & 3;

    float acc[4][4][4];
    #pragma unroll
    for (int i = 0; i < 4; i++)
        #pragma unroll
        for (int j = 0; j < 4; j++)
            #pragma unroll
            for (int r = 0; r < 4; r++) acc[i][j][r] = 0.f;

    const int T = d.K >> 6;

    const uint32_t AsU = (uint32_t)__cvta_generic_to_shared(Asb);
    const uint32_t BsU = (uint32_t)__cvta_generic_to_shared(Bsb);
    const int a_row = (lane & 15);
    const int a_col = (lane >> 4) << 3;
    const int b_row = (lane & 7) + ((lane >> 4) << 3);
    const int b_col = (lane & 8);
    uint32_t a_base[4], b_base[2];
    #pragma unroll
    for (int i = 0; i < 4; i++)
        a_base[i] = AsU + ((wm + i * 16 + a_row) * HT_LDS + a_col) * 2;
    #pragma unroll
    for (int q = 0; q < 2; q++)
        b_base[q] = BsU + ((wn + q * 16 + b_row) * HT_LDS + b_col) * 2;

    auto issue = [&](int ti) {
        const int buf = ti % N_STAGE;
        const int kt = ti * 64;
        __half* As = Asb + buf * HT_TILE;
        __half* Bs = Bsb + buf * HT_TILE;
        #pragma unroll
        for (int i = 0; i < 4; i++) {
            const int idx = tid + i * 256;
            const int r = idx >> 3, c = idx & 7;
            cp16(&As[r * HT_LDS + c * 8],
                 d.A + (size_t)(bm + r) * d.lda + kt + c * 8);
        }
        #pragma unroll
        for (int i = 0; i < 4; i++) {
            const int idx = tid + i * 256;
            const int r = idx >> 3, c = idx & 7;
            cp16(&Bs[r * HT_LDS + c * 8],
                 d.B + (size_t)(bn + r) * d.ldb + kt + c * 8);
        }
        asm volatile("cp.async.commit_group;\n");
    };

    issue(0);
    if (T > 1) issue(1);

    for (int ti = 0; ti < T; ti++) {
        // wait for tile ti's data (leave tile ti+1 pending if it exists)
        if (ti + 2 <= T) asm volatile("cp.async.wait_group 1;\n");
        else             asm volatile("cp.async.wait_group 0;\n");
        __syncthreads();   // data ready AND all warps done with buf (ti-1)%3

        if (ti + 2 < T) issue(ti + 2);   // overwrites buf (ti-1)%3 — safe

        const uint32_t bufOff = (uint32_t)(ti % N_STAGE) * (HT_TILE * 2);
        #pragma unroll
        for (int ks = 0; ks < 4; ks++) {
            const uint32_t kOff = bufOff + ks * 32;
            unsigned af[4][4], bf[4][2];
            #pragma unroll
            for (int i = 0; i < 4; i++)
                ldm_x4(af[i][0], af[i][1], af[i][2], af[i][3], a_base[i] + kOff);
            #pragma unroll
            for (int q = 0; q < 2; q++)
                ldm_x4(bf[2 * q][0], bf[2 * q][1], bf[2 * q + 1][0], bf[2 * q + 1][1],
                       b_base[q] + kOff);
            #pragma unroll
            for (int i = 0; i < 4; i++)
                #pragma unroll
                for (int j = 0; j < 4; j++)
                    asm volatile(
                        "mma.sync.aligned.m16n8k16.row.col.f32.f16.f16.f32 "
                        "{%0,%1,%2,%3},{%4,%5,%6,%7},{%8,%9},{%0,%1,%2,%3};\n"
                        : "+f"(acc[i][j][0]), "+f"(acc[i][j][1]),
                          "+f"(acc[i][j][2]), "+f"(acc[i][j][3])
                        : "r"(af[i][0]), "r"(af[i][1]), "r"(af[i][2]), "r"(af[i][3]),
                          "r"(bf[j][0]), "r"(bf[j][1]));
        }
    }

    #pragma unroll
    for (int i = 0; i < 4; i++) {
        #pragma unroll
        for (int j = 0; j < 4; j++) {
            const int row = bm + wm + i * 16 + g;
            const int col = bn + wn + j * 8 + t * 2;
            float b0 = 0.f, b1 = 0.f;
            if (d.bias) { b0 = d.bias[col]; b1 = d.bias[col + 1]; }
            const float v00 = acc[i][j][0] + b0, v01 = acc[i][j][1] + b1;
            const float v10 = acc[i][j][2] + b0, v11 = acc[i][j][3] + b1;
            if (d.Ch) {
                *(__half2*)(d.Ch + (size_t)row * d.ldc + col) = __floats2half2_rn(v00, v01);
                *(__half2*)(d.Ch + (size_t)(row + 8) * d.ldc + col) = __floats2half2_rn(v10, v11);
            } else {
                *(float2*)(d.C + (size_t)row * d.ldc + col) = make_float2(v00, v01);
                *(float2*)(d.C + (size_t)(row + 8) * d.ldc + col) = make_float2(v10, v11);
            }
        }
    }
}

// ---------------------------------------------------------------------------
// Fused biases
// ---------------------------------------------------------------------------
__global__ void __launch_bounds__(256) fbias_kernel(
    const float* __restrict__ Wk, const float* __restrict__ bk,
    const float* __restrict__ Wv, const float* __restrict__ bv,
    const float* __restrict__ bs, const float* __restrict__ semb)
{
    const int gw   = blockIdx.x * 8 + (threadIdx.x >> 5);
    const int lane = threadIdx.x & 31;
    const int which = gw / (SS * FD);
    const int rem   = gw - which * (SS * FD);
    const int i = rem >> 10;
    const int f = rem & 1023;
    const float* W = which ? Wv : Wk;
    const float* Wr  = W + (size_t)f * FD;
    const float* bsr = bs + i * FD;
    const float* ser = semb + i * FD;
    float sum = 0.f;
    for (int j = lane; j < FD; j += 32) sum += Wr[j] * (bsr[j] + ser[j]);
    sum = wredsum(sum);
    if (lane == 0) {
        if (which) g_fbv[rem] = sum + bv[f];
        else       g_fbk[rem] = sum + bk[f];
    }
}

// ---------------------------------------------------------------------------
// Attention + scale importance (K/V in half)
// ---------------------------------------------------------------------------
__global__ void __launch_bounds__(256) attn_kernel(
    const int* __restrict__ routes, const float* __restrict__ tptr)
{
    const int b = blockIdx.x;
    __shared__ float Qs[FD];
    __shared__ __half Ks[SS * FD];
    __shared__ __half Vs[SS * FD];
    __shared__ float ssi[SS];
    __shared__ int   rts[SS * LW];
    const int tid = threadIdx.x;

    ((float4*)Qs)[tid] = ((const float4*)(g_Q + (size_t)b * FD))[tid];
    const uint4* k4 = (const uint4*)(g_Kh + (size_t)b * SS * FD);
    const uint4* v4 = (const uint4*)(g_Vh + (size_t)b * SS * FD);
    #pragma unroll
    for (int i = 0; i < 3; i++) {
        const int idx = tid + 256 * i;
        if (idx < 640) {
            ((uint4*)Ks)[idx] = k4[idx];
            ((uint4*)Vs)[idx] = v4[idx];
        }
    }
    if (tid < SS * LW) rts[tid] = routes[tid];
    if (tid < SS) ssi[tid] = 0.f;
    __syncthreads();

    const float sc_mul = 1.0f / (8.0f * fabsf(*tptr));
    const int warp = tid >> 5, lane = tid & 31;

    for (int p = warp; p < HH * SS; p += 8) {
        const int h = p / SS, s = p - (p / SS) * SS;
        const float q0 = Qs[h * DD + lane];
        const float q1 = Qs[h * DD + 32 + lane];
        float scw[LW]; int jr[LW];
        #pragma unroll
        for (int w = 0; w < LW; w++) {
            const int j = rts[s * LW + w];
            jr[w] = j;
            const __half* kh = Ks + j * FD + h * DD;
            float d = q0 * __half2float(kh[lane]) + q1 * __half2float(kh[lane + 32]);
            d = wredsum(d);
            scw[w] = d * sc_mul;
        }
        const float m = fmaxf(scw[0], fmaxf(scw[1], scw[2]));
        float e0 = expf(scw[0] - m), e1 = expf(scw[1] - m), e2 = expf(scw[2] - m);
        const float inv = 1.0f / (e0 + e1 + e2);
        e0 *= inv; e1 *= inv; e2 *= inv;
        float o0 = 0.f, o1 = 0.f;
        {
            const __half* vh = Vs + jr[0] * FD + h * DD;
            o0 += e0 * __half2float(vh[lane]); o1 += e0 * __half2float(vh[lane + 32]);
        }
        {
            const __half* vh = Vs + jr[1] * FD + h * DD;
            o0 += e1 * __half2float(vh[lane]); o1 += e1 * __half2float(vh[lane + 32]);
        }
        {
            const __half* vh = Vs + jr[2] * FD + h * DD;
            o0 += e2 * __half2float(vh[lane]); o1 += e2 * __half2float(vh[lane + 32]);
        }
        float n2 = o0 * o0 + o1 * o1;
        n2 = wredsum(n2);
        if (lane == 0) atomicAdd(&ssi[s], sqrtf(n2));
    }
    __syncthreads();
    if (tid < SS) g_si[b * SS + tid] = ssi[tid] * (1.0f / (float)HH);
}

// ---------------------------------------------------------------------------
// Gate
// ---------------------------------------------------------------------------
__global__ void __launch_bounds__(128) gate_kernel(
    const float* __restrict__ gamma, const float* __restrict__ beta,
    const float* __restrict__ Wg2, const float* __restrict__ bg2,
    float* __restrict__ outTail)
{
    const int b = blockIdx.x, tid = threadIdx.x;
    const int warp = tid >> 5, lane = tid & 31;
    __shared__ float hs[GD];
    __shared__ float rbuf[32];

    const float4 v  = ((const float4*)(g_H + (size_t)b * GD))[tid];
    float s1 = v.x + v.y + v.z + v.w;
    float s2 = v.x * v.x + v.y * v.y + v.z * v.z + v.w * v.w;
    s1 = wredsum(s1); s2 = wredsum(s2);
    if (lane == 0) { rbuf[warp] = s1; rbuf[4 + warp] = s2; }
    __syncthreads();
    const float mu  = (rbuf[0] + rbuf[1] + rbuf[2] + rbuf[3]) * (1.0f / GD);
    const float ex2 = (rbuf[4] + rbuf[5] + rbuf[6] + rbuf[7]) * (1.0f / GD);
    const float rstd = rsqrtf(ex2 - mu * mu + 1e-5f);

    const float4 ga = ((const float4*)gamma)[tid];
    const float4 be = ((const float4*)beta)[tid];
    float4 o;
    {
        float x;
        x = (v.x - mu) * rstd * ga.x + be.x; o.x = 0.5f * x * (1.f + erff(x * 0.70710678118f));
        x = (v.y - mu) * rstd * ga.y + be.y; o.y = 0.5f * x * (1.f + erff(x * 0.70710678118f));
        x = (v.z - mu) * rstd * ga.z + be.z; o.z = 0.5f * x * (1.f + erff(x * 0.70710678118f));
        x = (v.w - mu) * rstd * ga.w + be.w; o.w = 0.5f * x * (1.f + erff(x * 0.70710678118f));
    }
    ((float4*)hs)[tid] = o;
    __syncthreads();

    float p[SS] = {0.f, 0.f, 0.f, 0.f, 0.f};
    #pragma unroll
    for (int r = 0; r < 4; r++) {
        const float x = hs[tid + 128 * r];
        #pragma unroll
        for (int s = 0; s < SS; s++) p[s] += x * Wg2[s * GD + tid + 128 * r];
    }
    #pragma unroll
    for (int s = 0; s < SS; s++) p[s] = wredsum(p[s]);
    if (lane == 0)
        #pragma unroll
        for (int s = 0; s < SS; s++) rbuf[8 + warp * SS + s] = p[s];
    __syncthreads();

    if (tid == 0) {
        float cs[SS];
        #pragma unroll
        for (int s = 0; s < SS; s++) {
            const float gl = rbuf[8 + s] + rbuf[13 + s] + rbuf[18 + s] + rbuf[23 + s] + bg2[s];
            cs[s] = 0.7f * g_si[b * SS + s] + 0.3f * gl;
        }
        float m = cs[0];
        #pragma unroll
        for (int s = 1; s < SS; s++) m = fmaxf(m, cs[s]);
        float e[SS], tot = 0.f;
        #pragma unroll
        for (int s = 0; s < SS; s++) { e[s] = expf(cs[s] - m); tot += e[s]; }
        const float inv = 1.0f / tot;
        #pragma unroll
        for (int s = 0; s < SS; s++) {
            const float w = e[s] * inv;
            g_aw[b * SS + s] = w;
            outTail[(size_t)b * SS + s] = w;
        }
    }
}

// ---------------------------------------------------------------------------
// combined_logits
// ---------------------------------------------------------------------------
__global__ void __launch_bounds__(256) combine_kernel(
    const float* __restrict__ l0, const float* __restrict__ l1,
    const float* __restrict__ l2, const float* __restrict__ l3,
    const float* __restrict__ l4, float* __restrict__ out)
{
    const int t = blockIdx.x * blockDim.x + threadIdx.x;
    if (t >= BQ * (CC / 4)) return;
    const int b = t / (CC / 4);
    const int c = t - b * (CC / 4);
    const float w0 = g_aw[b * SS + 0], w1 = g_aw[b * SS + 1], w2 = g_aw[b * SS + 2];
    const float w3 = g_aw[b * SS + 3], w4 = g_aw[b * SS + 4];
    const size_t idx = (size_t)b * (CC / 4) + c;
    const float4 a0 = ((const float4*)l0)[idx];
    const float4 a1 = ((const float4*)l1)[idx];
    const float4 a2 = ((const float4*)l2)[idx];
    const float4 a3 = ((const float4*)l3)[idx];
    const float4 a4 = ((const float4*)l4)[idx];
    float4 r;
    r.x = w0 * a0.x + w1 * a1.x + w2 * a2.x + w3 * a3.x + w4 * a4.x;
    r.y = w0 * a0.y + w1 * a1.y + w2 * a2.y + w3 * a3.y + w4 * a4.y;
    r.z = w0 * a0.z + w1 * a1.z + w2 * a2.z + w3 * a3.z + w4 * a4.z;
    r.w = w0 * a0.w + w1 * a1.w + w2 * a2.w + w3 * a3.w + w4 * a4.w;
    ((float4*)out)[idx] = r;
}

// ---------------------------------------------------------------------------
// kernel_launch
// ---------------------------------------------------------------------------
extern "C" void kernel_launch(void* const* d_in, const int* in_sizes, int n_in,
                              void* d_out, int out_size)
{
    (void)in_sizes; (void)n_in; (void)out_size;
    const float* features = (const float*)d_in[0];
    const float* sf[SS]     = {(const float*)d_in[1],  (const float*)d_in[2],
                               (const float*)d_in[3],  (const float*)d_in[4],
                               (const float*)d_in[5]};
    const float* logits[SS] = {(const float*)d_in[6],  (const float*)d_in[7],
                               (const float*)d_in[8],  (const float*)d_in[9],
                               (const float*)d_in[10]};
    const float* Ws[SS]     = {(const float*)d_in[11], (const float*)d_in[12],
                               (const float*)d_in[13], (const float*)d_in[14],
                               (const float*)d_in[15]};
    const float* bs   = (const float*)d_in[16];
    const float* semb = (const float*)d_in[17];
    const float* Wq   = (const float*)d_in[18];
    const float* bq   = (const float*)d_in[19];
    const float* Wk   = (const float*)d_in[20];
    const float* bk   = (const float*)d_in[21];
    const float* Wv   = (const float*)d_in[22];
    const float* bv   = (const float*)d_in[23];
    const float* Wg1  = (const float*)d_in[24];
    const float* bg1  = (const float*)d_in[25];
    const float* gam  = (const float*)d_in[26];
    const float* bet  = (const float*)d_in[27];
    const float* Wg2  = (const float*)d_in[28];
    const float* bg2  = (const float*)d_in[29];
    const float* temp = (const float*)d_in[30];
    const int*   routes = (const int*)d_in[31];

    __half *MKh, *MVh, *sfh, *feath, *Wqh, *Wg1h, *Kbh, *Vbh;
    float *fbk, *fbv, *Qb, *Hb;
    cudaGetSymbolAddress((void**)&MKh,   g_MKh);
    cudaGetSymbolAddress((void**)&MVh,   g_MVh);
    cudaGetSymbolAddress((void**)&sfh,   g_sfh);
    cudaGetSymbolAddress((void**)&feath, g_feath);
    cudaGetSymbolAddress((void**)&Wqh,   g_Wqh);
    cudaGetSymbolAddress((void**)&Wg1h,  g_Wg1h);
    cudaGetSymbolAddress((void**)&Kbh, g_Kh);
    cudaGetSymbolAddress((void**)&Vbh, g_Vh);
    cudaGetSymbolAddress((void**)&fbk, g_fbk);
    cudaGetSymbolAddress((void**)&fbv, g_fbv);
    cudaGetSymbolAddress((void**)&Qb,  g_Q);
    cudaGetSymbolAddress((void**)&Hb,  g_H);

    static const int SC[SS]  = {64, 128, 256, 512, 1024};
    static const int OFF[SS] = {0, 64, 192, 448, 960};

    // ---- 0) Convert fp32 -> fp16 operands ----
    {
        ConvParams cp{};
        for (int i = 0; i < SS; i++)
            cp.seg[i] = {sf[i], sfh + (size_t)BQ * OFF[i], (BQ * SC[i]) / 4};
        cp.seg[5] = {features, feath, (BQ * FD) / 4};
        cp.seg[6] = {Wq,  Wqh,  (FD * FD) / 4};
        cp.seg[7] = {Wg1, Wg1h, (GD * FD) / 4};
        convert_kernel<<<1184, 256>>>(cp);
    }

    // ---- 1) Batched prep ----
    {
        PrepParams p{};
        int x = 0;
        for (int i = 0; i < SS; i++) {
            p.seg[i] = {Wk, Ws[i], MKh + OFF[i], FD, SC[i], CSUM, FD, x};
            x += SC[i] / 64;
        }
        for (int i = 0; i < SS; i++) {
            p.seg[5 + i] = {Wv, Ws[i], MVh + OFF[i], FD, SC[i], CSUM, FD, x};
            x += SC[i] / 64;
        }
        gemm_nn_prep<<<dim3(x, FD / 128), 256>>>(p);
    }

    // ---- 2) Fused biases ----
    fbias_kernel<<<(2 * SS * FD) / 8, 256>>>(Wk, bk, Wv, bv, bs, semb);

    // ---- 3) Batched TN fp16 GEMM (ldmatrix, 3-stage) ----
    {
        SegHParams p{};
        int x = 0;
        for (int i = 0; i < SS; i++) {
            p.seg[i] = {sfh + (size_t)BQ * OFF[i], MKh + OFF[i], fbk + i * FD,
                        nullptr, Kbh + i * FD, SC[i], CSUM, SS * FD, SC[i], x};
            x += FD / 128;
        }
        for (int i = 0; i < SS; i++) {
            p.seg[5 + i] = {sfh + (size_t)BQ * OFF[i], MVh + OFF[i], fbv + i * FD,
                            nullptr, Vbh + i * FD, SC[i], CSUM, SS * FD, SC[i], x};
            x += FD / 128;
        }
        p.seg[10] = {feath, Wqh,  bq,  Qb, nullptr, FD, FD, FD, FD, x};
        x += FD / 128;
        p.seg[11] = {feath, Wg1h, bg1, Hb, nullptr, FD, FD, GD, FD, x};
        x += GD / 128;

        const int smemBytes = 2 * N_STAGE * HT_TILE * sizeof(__half);  // 110592
        cudaFuncSetAttribute(gemm_tn_f16,
                             cudaFuncAttributeMaxDynamicSharedMemorySize, smemBytes);
        gemm_tn_f16<<<dim3(x, BQ / 128), 256, smemBytes>>>(p);
    }

    // ---- 4) Attention + scale importance ----
    attn_kernel<<<BQ, 256>>>(routes, temp);

    // ---- 5) Gate + softmax ----
    float* out = (float*)d_out;
    gate_kernel<<<BQ, 128>>>(gam, bet, Wg2, bg2, out + (size_t)BQ * CC);

    // ---- 6) combined_logits ----
    combine_kernel<<<(BQ * (CC / 4) + 255) / 256, 256>>>(logits[0], logits[1], logits[2],
                                                         logits[3], logits[4], out);
}

// round 11
// speedup vs baseline: 1.0280x; 1.0280x over previous
#include <cuda_runtime.h>
#include <cuda_fp16.h>
#include <cstdint>

#define BQ    8192
#define FD    1024
#define HH    16
#define DD    64
#define SS    5
#define LW    3
#define CC    1000
#define GD    512
#define CSUM  1984   // 64+128+256+512+1024

// ---------------------------------------------------------------------------
// Scratch
// ---------------------------------------------------------------------------
__device__ __half g_MKh[FD * CSUM];
__device__ __half g_MVh[FD * CSUM];
__device__ __half g_sfh[(size_t)BQ * CSUM];
__device__ __half g_feath[(size_t)BQ * FD];
__device__ __half g_Wqh[FD * FD];
__device__ __half g_Wg1h[GD * FD];
__device__ float g_fbk[SS * FD];
__device__ float g_fbv[SS * FD];
__device__ __half g_Kh[(size_t)BQ * SS * FD];
__device__ __half g_Vh[(size_t)BQ * SS * FD];
__device__ float g_Q[(size_t)BQ * FD];
__device__ float g_H[(size_t)BQ * GD];

// ---------------------------------------------------------------------------
// Helpers
// ---------------------------------------------------------------------------
__device__ __forceinline__ unsigned f2tf(float x) {
    unsigned r;
    asm("cvt.rna.tf32.f32 %0, %1;" : "=r"(r) : "f"(x));
    return r;
}
__device__ __forceinline__ float wredsum(float v) {
    #pragma unroll
    for (int o = 16; o; o >>= 1) v += __shfl_xor_sync(0xffffffffu, v, o);
    return v;
}
__device__ __forceinline__ void cp16(void* s, const void* g) {
    uint32_t sa = (uint32_t)__cvta_generic_to_shared(s);
    asm volatile("cp.async.cg.shared.global [%0], [%1], 16;\n" :: "r"(sa), "l"(g));
}
__device__ __forceinline__ void ldm_x4(unsigned& r0, unsigned& r1, unsigned& r2, unsigned& r3,
                                       uint32_t addr) {
    asm volatile("ldmatrix.sync.aligned.m8n8.x4.shared.b16 {%0,%1,%2,%3}, [%4];"
                 : "=r"(r0), "=r"(r1), "=r"(r2), "=r"(r3) : "r"(addr));
}

// ---------------------------------------------------------------------------
// f32 -> f16 conversion (8 segments, grid-stride)
// ---------------------------------------------------------------------------
struct ConvSeg { const float* src; __half* dst; int n4; };
struct ConvParams { ConvSeg seg[8]; };

__global__ void __launch_bounds__(256) convert_kernel(ConvParams p)
{
    const int stride = gridDim.x * blockDim.x;
    const int t0 = blockIdx.x * blockDim.x + threadIdx.x;
    #pragma unroll
    for (int s = 0; s < 8; s++) {
        const float* src = p.seg[s].src;
        __half* dst = p.seg[s].dst;
        const int n4 = p.seg[s].n4;
        for (int i = t0; i < n4; i += stride) {
            const float4 v = ((const float4*)src)[i];
            ((__half2*)dst)[2 * i + 0] = __floats2half2_rn(v.x, v.y);
            ((__half2*)dst)[2 * i + 1] = __floats2half2_rn(v.z, v.w);
        }
    }
}

// ---------------------------------------------------------------------------
// Batched NN GEMM (prep, tf32 mma.sync): writes half MK/MV
// ---------------------------------------------------------------------------
struct PrepSeg {
    const float* A;
    const float* B;
    __half*      C;
    int lda, ldb, ldc, K, xStart;
};
struct PrepParams { PrepSeg seg[10]; };

__global__ void __launch_bounds__(256) gemm_nn_prep(PrepParams p)
{
    __shared__ float As[128 * 36];
    __shared__ float Bs[64 * 36];

    const int bx = blockIdx.x;
    int si = 0;
    #pragma unroll
    for (int i = 1; i < 10; i++)
        if (bx >= p.seg[i].xStart) si = i;
    const PrepSeg d = p.seg[si];

    const int bn = (bx - d.xStart) * 64;
    const int bm = blockIdx.y * 128;
    const int tid  = threadIdx.x;
    const int warp = tid >> 5, lane = tid & 31;
    const int wm = (warp & 3) * 32;
    const int wn = (warp >> 2) * 32;
    const int g = lane >> 2, t = lane & 3;
    const int arow = tid >> 3;
    const int acol = (tid & 7) * 4;

    float acc[2][4][4];
    #pragma unroll
    for (int i = 0; i < 2; i++)
        #pragma unroll
        for (int j = 0; j < 4; j++)
            #pragma unroll
            for (int r = 0; r < 4; r++) acc[i][j][r] = 0.f;

    for (int kt = 0; kt < d.K; kt += 32) {
        #pragma unroll
        for (int r = 0; r < 4; r++) {
            const float4 v = *(const float4*)(d.A + (size_t)(bm + arow + 32 * r) * d.lda + kt + acol);
            float4 w;
            w.x = __uint_as_float(f2tf(v.x));
            w.y = __uint_as_float(f2tf(v.y));
            w.z = __uint_as_float(f2tf(v.z));
            w.w = __uint_as_float(f2tf(v.w));
            *(float4*)(&As[(arow + 32 * r) * 36 + acol]) = w;
        }
        #pragma unroll
        for (int r = 0; r < 2; r++) {
            const int kk = (tid >> 4) + 16 * r;
            const int nn = (tid & 15) * 4;
            const float4 v = *(const float4*)(d.B + (size_t)(kt + kk) * d.ldb + bn + nn);
            Bs[(nn + 0) * 36 + kk] = __uint_as_float(f2tf(v.x));
            Bs[(nn + 1) * 36 + kk] = __uint_as_float(f2tf(v.y));
            Bs[(nn + 2) * 36 + kk] = __uint_as_float(f2tf(v.z));
            Bs[(nn + 3) * 36 + kk] = __uint_as_float(f2tf(v.w));
        }
        __syncthreads();

        #pragma unroll
        for (int ks = 0; ks < 4; ks++) {
            const int k0 = ks * 8;
            unsigned af[2][4], bf[4][2];
            #pragma unroll
            for (int i = 0; i < 2; i++) {
                const int r0 = wm + i * 16;
                af[i][0] = __float_as_uint(As[(r0 + g    ) * 36 + k0 + t]);
                af[i][1] = __float_as_uint(As[(r0 + 8 + g) * 36 + k0 + t]);
                af[i][2] = __float_as_uint(As[(r0 + g    ) * 36 + k0 + t + 4]);
                af[i][3] = __float_as_uint(As[(r0 + 8 + g) * 36 + k0 + t + 4]);
            }
            #pragma unroll
            for (int j = 0; j < 4; j++) {
                const int c0 = wn + j * 8;
                bf[j][0] = __float_as_uint(Bs[(c0 + g) * 36 + k0 + t]);
                bf[j][1] = __float_as_uint(Bs[(c0 + g) * 36 + k0 + t + 4]);
            }
            #pragma unroll
            for (int i = 0; i < 2; i++)
                #pragma unroll
                for (int j = 0; j < 4; j++)
                    asm volatile(
                        "mma.sync.aligned.m16n8k8.row.col.f32.tf32.tf32.f32 "
                        "{%0,%1,%2,%3},{%4,%5,%6,%7},{%8,%9},{%0,%1,%2,%3};\n"
                        : "+f"(acc[i][j][0]), "+f"(acc[i][j][1]),
                          "+f"(acc[i][j][2]), "+f"(acc[i][j][3])
                        : "r"(af[i][0]), "r"(af[i][1]), "r"(af[i][2]), "r"(af[i][3]),
                          "r"(bf[j][0]), "r"(bf[j][1]));
        }
        __syncthreads();
    }

    #pragma unroll
    for (int i = 0; i < 2; i++) {
        #pragma unroll
        for (int j = 0; j < 4; j++) {
            const int row = bm + wm + i * 16 + g;
            const int col = bn + wn + j * 8 + t * 2;
            *(__half2*)(d.C + (size_t)row * d.ldc + col) =
                __floats2half2_rn(acc[i][j][0], acc[i][j][1]);
            *(__half2*)(d.C + (size_t)(row + 8) * d.ldc + col) =
                __floats2half2_rn(acc[i][j][2], acc[i][j][3]);
        }
    }
}

// ---------------------------------------------------------------------------
// Batched TN GEMM, fp16 m16n8k16 + ldmatrix.x4, fp32 accum.
// 3-stage cp.async pipeline, one __syncthreads per tile. 2 CTAs/SM.
// ---------------------------------------------------------------------------
struct SegH {
    const __half* A;
    const __half* B;
    const float*  bias;
    float*        C;
    __half*       Ch;
    int lda, ldb, ldc, K, xStart;
};
struct SegHParams { SegH seg[12]; };

#define HT_ROWS 128
#define HT_LDS  72
#define HT_TILE (HT_ROWS * HT_LDS)
#define N_STAGE 3

__global__ void __launch_bounds__(256, 2) gemm_tn_f16(SegHParams p)
{
    extern __shared__ __half smemH[];
    __half* Asb = smemH;
    __half* Bsb = smemH + N_STAGE * HT_TILE;

    const int bx = blockIdx.x;
    int si = 0;
    #pragma unroll
    for (int i = 1; i < 12; i++)
        if (bx >= p.seg[i].xStart) si = i;
    const SegH d = p.seg[si];

    const int bn = (bx - d.xStart) * 128;
    const int bm = blockIdx.y * 128;
    const int tid  = threadIdx.x;
    const int warp = tid >> 5, lane = tid & 31;
    const int wm = (warp & 1) * 64;
    const int wn = (warp >> 1) * 32;
    const int g = lane >> 2, t = lane & 3;

    float acc[4][4][4];
    #pragma unroll
    for (int i = 0; i < 4; i++)
        #pragma unroll
        for (int j = 0; j < 4; j++)
            #pragma unroll
            for (int r = 0; r < 4; r++) acc[i][j][r] = 0.f;

    const int T = d.K >> 6;

    const uint32_t AsU = (uint32_t)__cvta_generic_to_shared(Asb);
    const uint32_t BsU = (uint32_t)__cvta_generic_to_shared(Bsb);
    const int a_row = (lane & 15);
    const int a_col = (lane >> 4) << 3;
    const int b_row = (lane & 7) + ((lane >> 4) << 3);
    const int b_col = (lane & 8);
    uint32_t a_base[4], b_base[2];
    #pragma unroll
    for (int i = 0; i < 4; i++)
        a_base[i] = AsU + ((wm + i * 16 + a_row) * HT_LDS + a_col) * 2;
    #pragma unroll
    for (int q = 0; q < 2; q++)
        b_base[q] = BsU + ((wn + q * 16 + b_row) * HT_LDS + b_col) * 2;

    auto issue = [&](int ti) {
        const int buf = ti % N_STAGE;
        const int kt = ti * 64;
        __half* As = Asb + buf * HT_TILE;
        __half* Bs = Bsb + buf * HT_TILE;
        #pragma unroll
        for (int i = 0; i < 4; i++) {
            const int idx = tid + i * 256;
            const int r = idx >> 3, c = idx & 7;
            cp16(&As[r * HT_LDS + c * 8],
                 d.A + (size_t)(bm + r) * d.lda + kt + c * 8);
        }
        #pragma unroll
        for (int i = 0; i < 4; i++) {
            const int idx = tid + i * 256;
            const int r = idx >> 3, c = idx & 7;
            cp16(&Bs[r * HT_LDS + c * 8],
                 d.B + (size_t)(bn + r) * d.ldb + kt + c * 8);
        }
        asm volatile("cp.async.commit_group;\n");
    };

    issue(0);
    if (T > 1) issue(1);

    for (int ti = 0; ti < T; ti++) {
        if (ti + 2 <= T) asm volatile("cp.async.wait_group 1;\n");
        else             asm volatile("cp.async.wait_group 0;\n");
        __syncthreads();

        if (ti + 2 < T) issue(ti + 2);

        const uint32_t bufOff = (uint32_t)(ti % N_STAGE) * (HT_TILE * 2);
        #pragma unroll
        for (int ks = 0; ks < 4; ks++) {
            const uint32_t kOff = bufOff + ks * 32;
            unsigned af[4][4], bf[4][2];
            #pragma unroll
            for (int i = 0; i < 4; i++)
                ldm_x4(af[i][0], af[i][1], af[i][2], af[i][3], a_base[i] + kOff);
            #pragma unroll
            for (int q = 0; q < 2; q++)
                ldm_x4(bf[2 * q][0], bf[2 * q][1], bf[2 * q + 1][0], bf[2 * q + 1][1],
                       b_base[q] + kOff);
            #pragma unroll
            for (int i = 0; i < 4; i++)
                #pragma unroll
                for (int j = 0; j < 4; j++)
                    asm volatile(
                        "mma.sync.aligned.m16n8k16.row.col.f32.f16.f16.f32 "
                        "{%0,%1,%2,%3},{%4,%5,%6,%7},{%8,%9},{%0,%1,%2,%3};\n"
                        : "+f"(acc[i][j][0]), "+f"(acc[i][j][1]),
                          "+f"(acc[i][j][2]), "+f"(acc[i][j][3])
                        : "r"(af[i][0]), "r"(af[i][1]), "r"(af[i][2]), "r"(af[i][3]),
                          "r"(bf[j][0]), "r"(bf[j][1]));
        }
    }

    #pragma unroll
    for (int i = 0; i < 4; i++) {
        #pragma unroll
        for (int j = 0; j < 4; j++) {
            const int row = bm + wm + i * 16 + g;
            const int col = bn + wn + j * 8 + t * 2;
            float b0 = 0.f, b1 = 0.f;
            if (d.bias) { b0 = d.bias[col]; b1 = d.bias[col + 1]; }
            const float v00 = acc[i][j][0] + b0, v01 = acc[i][j][1] + b1;
            const float v10 = acc[i][j][2] + b0, v11 = acc[i][j][3] + b1;
            if (d.Ch) {
                *(__half2*)(d.Ch + (size_t)row * d.ldc + col) = __floats2half2_rn(v00, v01);
                *(__half2*)(d.Ch + (size_t)(row + 8) * d.ldc + col) = __floats2half2_rn(v10, v11);
            } else {
                *(float2*)(d.C + (size_t)row * d.ldc + col) = make_float2(v00, v01);
                *(float2*)(d.C + (size_t)(row + 8) * d.ldc + col) = make_float2(v10, v11);
            }
        }
    }
}

// ---------------------------------------------------------------------------
// Fused biases
// ---------------------------------------------------------------------------
__global__ void __launch_bounds__(256) fbias_kernel(
    const float* __restrict__ Wk, const float* __restrict__ bk,
    const float* __restrict__ Wv, const float* __restrict__ bv,
    const float* __restrict__ bs, const float* __restrict__ semb)
{
    const int gw   = blockIdx.x * 8 + (threadIdx.x >> 5);
    const int lane = threadIdx.x & 31;
    const int which = gw / (SS * FD);
    const int rem   = gw - which * (SS * FD);
    const int i = rem >> 10;
    const int f = rem & 1023;
    const float* W = which ? Wv : Wk;
    const float* Wr  = W + (size_t)f * FD;
    const float* bsr = bs + i * FD;
    const float* ser = semb + i * FD;
    float sum = 0.f;
    for (int j = lane; j < FD; j += 32) sum += Wr[j] * (bsr[j] + ser[j]);
    sum = wredsum(sum);
    if (lane == 0) {
        if (which) g_fbv[rem] = sum + bv[f];
        else       g_fbk[rem] = sum + bk[f];
    }
}

// ---------------------------------------------------------------------------
// FUSED: attention + scale importance + gate (LN/GELU/Wg2) + softmax + combine
// One block (256 thr) per batch row b.
// ---------------------------------------------------------------------------
__global__ void __launch_bounds__(256) fused_tail_kernel(
    const int* __restrict__ routes, const float* __restrict__ tptr,
    const float* __restrict__ gamma, const float* __restrict__ beta,
    const float* __restrict__ Wg2, const float* __restrict__ bg2,
    const float* __restrict__ l0, const float* __restrict__ l1,
    const float* __restrict__ l2, const float* __restrict__ l3,
    const float* __restrict__ l4, float* __restrict__ out)
{
    const int b = blockIdx.x;
    __shared__ float Qs[FD];
    __shared__ __half Ks[SS * FD];
    __shared__ __half Vs[SS * FD];
    __shared__ float hs[GD];
    __shared__ float ssi[SS];
    __shared__ float aws[SS];
    __shared__ int   rts[SS * LW];
    __shared__ float rbuf[64];
    const int tid = threadIdx.x;
    const int warp = tid >> 5, lane = tid & 31;

    // ---- loads ----
    ((float4*)Qs)[tid] = ((const float4*)(g_Q + (size_t)b * FD))[tid];
    const uint4* k4 = (const uint4*)(g_Kh + (size_t)b * SS * FD);
    const uint4* v4 = (const uint4*)(g_Vh + (size_t)b * SS * FD);
    #pragma unroll
    for (int i = 0; i < 3; i++) {
        const int idx = tid + 256 * i;
        if (idx < 640) {
            ((uint4*)Ks)[idx] = k4[idx];
            ((uint4*)Vs)[idx] = v4[idx];
        }
    }
    if (tid < SS * LW) rts[tid] = routes[tid];
    if (tid < SS) ssi[tid] = 0.f;
    const float2 hv = ((const float2*)(g_H + (size_t)b * GD))[tid];  // 512 floats
    __syncthreads();

    // ---- Phase A: attention + scale importance ----
    const float sc_mul = 1.0f / (8.0f * fabsf(*tptr));
    for (int p = warp; p < HH * SS; p += 8) {
        const int h = p / SS, s = p - (p / SS) * SS;
        const float q0 = Qs[h * DD + lane];
        const float q1 = Qs[h * DD + 32 + lane];
        float scw[LW]; int jr[LW];
        #pragma unroll
        for (int w = 0; w < LW; w++) {
            const int j = rts[s * LW + w];
            jr[w] = j;
            const __half* kh = Ks + j * FD + h * DD;
            float d = q0 * __half2float(kh[lane]) + q1 * __half2float(kh[lane + 32]);
            d = wredsum(d);
            scw[w] = d * sc_mul;
        }
        const float m = fmaxf(scw[0], fmaxf(scw[1], scw[2]));
        float e0 = expf(scw[0] - m), e1 = expf(scw[1] - m), e2 = expf(scw[2] - m);
        const float inv = 1.0f / (e0 + e1 + e2);
        e0 *= inv; e1 *= inv; e2 *= inv;
        float o0 = 0.f, o1 = 0.f;
        {
            const __half* vh = Vs + jr[0] * FD + h * DD;
            o0 += e0 * __half2float(vh[lane]); o1 += e0 * __half2float(vh[lane + 32]);
        }
        {
            const __half* vh = Vs + jr[1] * FD + h * DD;
            o0 += e1 * __half2float(vh[lane]); o1 += e1 * __half2float(vh[lane + 32]);
        }
        {
            const __half* vh = Vs + jr[2] * FD + h * DD;
            o0 += e2 * __half2float(vh[lane]); o1 += e2 * __half2float(vh[lane + 32]);
        }
        float n2 = o0 * o0 + o1 * o1;
        n2 = wredsum(n2);
        if (lane == 0) atomicAdd(&ssi[s], sqrtf(n2));
    }

    // ---- Phase B: gate LayerNorm + GELU ----
    {
        float s1 = hv.x + hv.y;
        float s2 = hv.x * hv.x + hv.y * hv.y;
        s1 = wredsum(s1); s2 = wredsum(s2);
        if (lane == 0) { rbuf[warp] = s1; rbuf[8 + warp] = s2; }
    }
    __syncthreads();   // also closes Phase A's ssi atomics
    {
        float su = 0.f, sq = 0.f;
        #pragma unroll
        for (int w = 0; w < 8; w++) { su += rbuf[w]; sq += rbuf[8 + w]; }
        const float mu  = su * (1.0f / GD);
        const float ex2 = sq * (1.0f / GD);
        const float rstd = rsqrtf(ex2 - mu * mu + 1e-5f);

        const float2 ga = ((const float2*)gamma)[tid];
        const float2 be = ((const float2*)beta)[tid];
        float x0 = (hv.x - mu) * rstd * ga.x + be.x;
        float x1 = (hv.y - mu) * rstd * ga.y + be.y;
        hs[2 * tid + 0] = 0.5f * x0 * (1.f + erff(x0 * 0.70710678118f));
        hs[2 * tid + 1] = 0.5f * x1 * (1.f + erff(x1 * 0.70710678118f));
    }
    __syncthreads();

    // ---- Phase B2: gate logits (Wg2 dot) ----
    {
        const float xa = hs[tid];
        const float xb = hs[tid + 256];
        float p[SS];
        #pragma unroll
        for (int s = 0; s < SS; s++)
            p[s] = xa * Wg2[s * GD + tid] + xb * Wg2[s * GD + tid + 256];
        #pragma unroll
        for (int s = 0; s < SS; s++) p[s] = wredsum(p[s]);
        if (lane == 0)
            #pragma unroll
            for (int s = 0; s < SS; s++) rbuf[16 + warp * SS + s] = p[s];
    }
    __syncthreads();

    if (tid == 0) {
        float cs[SS];
        #pragma unroll
        for (int s = 0; s < SS; s++) {
            float gl = bg2[s];
            #pragma unroll
            for (int w = 0; w < 8; w++) gl += rbuf[16 + w * SS + s];
            cs[s] = 0.7f * (ssi[s] * (1.0f / (float)HH)) + 0.3f * gl;
        }
        float m = cs[0];
        #pragma unroll
        for (int s = 1; s < SS; s++) m = fmaxf(m, cs[s]);
        float e[SS], tot = 0.f;
        #pragma unroll
        for (int s = 0; s < SS; s++) { e[s] = expf(cs[s] - m); tot += e[s]; }
        const float inv = 1.0f / tot;
        #pragma unroll
        for (int s = 0; s < SS; s++) aws[s] = e[s] * inv;
    }
    __syncthreads();

    // ---- Phase C: combine logits + write outputs ----
    const float w0 = aws[0], w1 = aws[1], w2 = aws[2], w3 = aws[3], w4 = aws[4];
    if (tid < SS) out[(size_t)BQ * CC + (size_t)b * SS + tid] = aws[tid];
    if (tid < CC / 4) {
        const size_t idx = (size_t)b * (CC / 4) + tid;
        const float4 a0 = ((const float4*)l0)[idx];
        const float4 a1 = ((const float4*)l1)[idx];
        const float4 a2 = ((const float4*)l2)[idx];
        const float4 a3 = ((const float4*)l3)[idx];
        const float4 a4 = ((const float4*)l4)[idx];
        float4 r;
        r.x = w0 * a0.x + w1 * a1.x + w2 * a2.x + w3 * a3.x + w4 * a4.x;
        r.y = w0 * a0.y + w1 * a1.y + w2 * a2.y + w3 * a3.y + w4 * a4.y;
        r.z = w0 * a0.z + w1 * a1.z + w2 * a2.z + w3 * a3.z + w4 * a4.z;
        r.w = w0 * a0.w + w1 * a1.w + w2 * a2.w + w3 * a3.w + w4 * a4.w;
        ((float4*)out)[idx] = r;
    }
}

// ---------------------------------------------------------------------------
// kernel_launch
// ---------------------------------------------------------------------------
extern "C" void kernel_launch(void* const* d_in, const int* in_sizes, int n_in,
                              void* d_out, int out_size)
{
    (void)in_sizes; (void)n_in; (void)out_size;
    const float* features = (const float*)d_in[0];
    const float* sf[SS]     = {(const float*)d_in[1],  (const float*)d_in[2],
                               (const float*)d_in[3],  (const float*)d_in[4],
                               (const float*)d_in[5]};
    const float* logits[SS] = {(const float*)d_in[6],  (const float*)d_in[7],
                               (const float*)d_in[8],  (const float*)d_in[9],
                               (const float*)d_in[10]};
    const float* Ws[SS]     = {(const float*)d_in[11], (const float*)d_in[12],
                               (const float*)d_in[13], (const float*)d_in[14],
                               (const float*)d_in[15]};
    const float* bs   = (const float*)d_in[16];
    const float* semb = (const float*)d_in[17];
    const float* Wq   = (const float*)d_in[18];
    const float* bq   = (const float*)d_in[19];
    const float* Wk   = (const float*)d_in[20];
    const float* bk   = (const float*)d_in[21];
    const float* Wv   = (const float*)d_in[22];
    const float* bv   = (const float*)d_in[23];
    const float* Wg1  = (const float*)d_in[24];
    const float* bg1  = (const float*)d_in[25];
    const float* gam  = (const float*)d_in[26];
    const float* bet  = (const float*)d_in[27];
    const float* Wg2  = (const float*)d_in[28];
    const float* bg2  = (const float*)d_in[29];
    const float* temp = (const float*)d_in[30];
    const int*   routes = (const int*)d_in[31];

    __half *MKh, *MVh, *sfh, *feath, *Wqh, *Wg1h, *Kbh, *Vbh;
    float *fbk, *fbv, *Qb, *Hb;
    cudaGetSymbolAddress((void**)&MKh,   g_MKh);
    cudaGetSymbolAddress((void**)&MVh,   g_MVh);
    cudaGetSymbolAddress((void**)&sfh,   g_sfh);
    cudaGetSymbolAddress((void**)&feath, g_feath);
    cudaGetSymbolAddress((void**)&Wqh,   g_Wqh);
    cudaGetSymbolAddress((void**)&Wg1h,  g_Wg1h);
    cudaGetSymbolAddress((void**)&Kbh, g_Kh);
    cudaGetSymbolAddress((void**)&Vbh, g_Vh);
    cudaGetSymbolAddress((void**)&fbk, g_fbk);
    cudaGetSymbolAddress((void**)&fbv, g_fbv);
    cudaGetSymbolAddress((void**)&Qb,  g_Q);
    cudaGetSymbolAddress((void**)&Hb,  g_H);

    static const int SC[SS]  = {64, 128, 256, 512, 1024};
    static const int OFF[SS] = {0, 64, 192, 448, 960};

    // ---- 0) Convert fp32 -> fp16 operands ----
    {
        ConvParams cp{};
        for (int i = 0; i < SS; i++)
            cp.seg[i] = {sf[i], sfh + (size_t)BQ * OFF[i], (BQ * SC[i]) / 4};
        cp.seg[5] = {features, feath, (BQ * FD) / 4};
        cp.seg[6] = {Wq,  Wqh,  (FD * FD) / 4};
        cp.seg[7] = {Wg1, Wg1h, (GD * FD) / 4};
        convert_kernel<<<1184, 256>>>(cp);
    }

    // ---- 1) Batched prep ----
    {
        PrepParams p{};
        int x = 0;
        for (int i = 0; i < SS; i++) {
            p.seg[i] = {Wk, Ws[i], MKh + OFF[i], FD, SC[i], CSUM, FD, x};
            x += SC[i] / 64;
        }
        for (int i = 0; i < SS; i++) {
            p.seg[5 + i] = {Wv, Ws[i], MVh + OFF[i], FD, SC[i], CSUM, FD, x};
            x += SC[i] / 64;
        }
        gemm_nn_prep<<<dim3(x, FD / 128), 256>>>(p);
    }

    // ---- 2) Fused biases ----
    fbias_kernel<<<(2 * SS * FD) / 8, 256>>>(Wk, bk, Wv, bv, bs, semb);

    // ---- 3) Batched TN fp16 GEMM (ldmatrix, 3-stage) ----
    {
        SegHParams p{};
        int x = 0;
        for (int i = 0; i < SS; i++) {
            p.seg[i] = {sfh + (size_t)BQ * OFF[i], MKh + OFF[i], fbk + i * FD,
                        nullptr, Kbh + i * FD, SC[i], CSUM, SS * FD, SC[i], x};
            x += FD / 128;
        }
        for (int i = 0; i < SS; i++) {
            p.seg[5 + i] = {sfh + (size_t)BQ * OFF[i], MVh + OFF[i], fbv + i * FD,
                            nullptr, Vbh + i * FD, SC[i], CSUM, SS * FD, SC[i], x};
            x += FD / 128;
        }
        p.seg[10] = {feath, Wqh,  bq,  Qb, nullptr, FD, FD, FD, FD, x};
        x += FD / 128;
        p.seg[11] = {feath, Wg1h, bg1, Hb, nullptr, FD, FD, GD, FD, x};
        x += GD / 128;

        const int smemBytes = 2 * N_STAGE * HT_TILE * sizeof(__half);  // 110592
        cudaFuncSetAttribute(gemm_tn_f16,
                             cudaFuncAttributeMaxDynamicSharedMemorySize, smemBytes);
        gemm_tn_f16<<<dim3(x, BQ / 128), 256, smemBytes>>>(p);
    }

    // ---- 4) Fused tail: attention + gate + softmax + combine ----
    fused_tail_kernel<<<BQ, 256>>>(routes, temp, gam, bet, Wg2, bg2,
                                   logits[0], logits[1], logits[2],
                                   logits[3], logits[4], (float*)d_out);
}

// round 13
// speedup vs baseline: 1.2208x; 1.1875x over previous
#include <cuda_runtime.h>
#include <cuda_fp16.h>
#include <cstdint>

#define BQ    8192
#define FD    1024
#define HH    16
#define DD    64
#define SS    5
#define LW    3
#define CC    1000
#define GD    512
#define CSUM  1984   // 64+128+256+512+1024
#define PSUM  2048   // padded: 128+128+256+512+1024

// ---------------------------------------------------------------------------
// Scratch
// ---------------------------------------------------------------------------
__device__ __half g_MKp[(size_t)FD * PSUM];    // padded MK (half)
__device__ __half g_MVp[(size_t)FD * PSUM];
__device__ __half g_WsT[(size_t)PSUM * FD];    // transposed+padded Ws (half)
__device__ __half g_sfh[(size_t)BQ * CSUM];
__device__ __half g_feath[(size_t)BQ * FD];
__device__ __half g_Wqh[FD * FD];
__device__ __half g_Wg1h[GD * FD];
__device__ __half g_Wkh[FD * FD];
__device__ __half g_Wvh[FD * FD];
__device__ float g_fbk[SS * FD];
__device__ float g_fbv[SS * FD];
__device__ __half g_Kh[(size_t)BQ * SS * FD];
__device__ __half g_Vh[(size_t)BQ * SS * FD];
__device__ float g_Q[(size_t)BQ * FD];
__device__ float g_H[(size_t)BQ * GD];

// ---------------------------------------------------------------------------
// Helpers
// ---------------------------------------------------------------------------
__device__ __forceinline__ float wredsum(float v) {
    #pragma unroll
    for (int o = 16; o; o >>= 1) v += __shfl_xor_sync(0xffffffffu, v, o);
    return v;
}
__device__ __forceinline__ void cp16(void* s, const void* g) {
    uint32_t sa = (uint32_t)__cvta_generic_to_shared(s);
    asm volatile("cp.async.cg.shared.global [%0], [%1], 16;\n" :: "r"(sa), "l"(g));
}
__device__ __forceinline__ void ldm_x4(unsigned& r0, unsigned& r1, unsigned& r2, unsigned& r3,
                                       uint32_t addr) {
    asm volatile("ldmatrix.sync.aligned.m8n8.x4.shared.b16 {%0,%1,%2,%3}, [%4];"
                 : "=r"(r0), "=r"(r1), "=r"(r2), "=r"(r3) : "r"(addr));
}

// ---------------------------------------------------------------------------
// f32 -> f16 conversion (10 segments, grid-stride)
// ---------------------------------------------------------------------------
struct ConvSeg { const float* src; __half* dst; int n4; };
struct ConvParams { ConvSeg seg[10]; };

__global__ void __launch_bounds__(256) convert_kernel(ConvParams p)
{
    const int stride = gridDim.x * blockDim.x;
    const int t0 = blockIdx.x * blockDim.x + threadIdx.x;
    #pragma unroll
    for (int s = 0; s < 10; s++) {
        const float* src = p.seg[s].src;
        __half* dst = p.seg[s].dst;
        const int n4 = p.seg[s].n4;
        for (int i = t0; i < n4; i += stride) {
            const float4 v = ((const float4*)src)[i];
            ((__half2*)dst)[2 * i + 0] = __floats2half2_rn(v.x, v.y);
            ((__half2*)dst)[2 * i + 1] = __floats2half2_rn(v.z, v.w);
        }
    }
}

// ---------------------------------------------------------------------------
// Transpose Ws_i [FD, sc] f32 -> WsT [P, FD] half (rows >= sc zero-filled)
// 32x32 tiles, 256 threads. blocks per segment = 32 * (P/32), j-tile fastest.
// ---------------------------------------------------------------------------
struct TSeg { const float* src; __half* dst; int sc; int xStart; };
struct TParams { TSeg seg[SS]; };

__global__ void __launch_bounds__(256) transpose_kernel(TParams p)
{
    const int bx = blockIdx.x;
    int si = 0;
    #pragma unroll
    for (int i = 1; i < SS; i++)
        if (bx >= p.seg[i].xStart) si = i;
    const TSeg d = p.seg[si];

    const int local = bx - d.xStart;
    const int jt = local & 31;        // FD/32 = 32 j-tiles
    const int nt = local >> 5;
    const int tx = threadIdx.x & 31, ty = threadIdx.x >> 5;

    __shared__ float tile[32][33];
    const int n_in = nt * 32 + tx;
    #pragma unroll
    for (int r = 0; r < 4; r++) {
        const int j = jt * 32 + ty + r * 8;
        tile[ty + r * 8][tx] = (n_in < d.sc) ? d.src[(size_t)j * d.sc + n_in] : 0.f;
    }
    __syncthreads();
    const int j_out = jt * 32 + tx;
    #pragma unroll
    for (int r = 0; r < 4; r++) {
        const int n = nt * 32 + ty + r * 8;
        d.dst[(size_t)n * FD + j_out] = __float2half(tile[tx][ty + r * 8]);
    }
}

// ---------------------------------------------------------------------------
// Batched TN GEMM, fp16 m16n8k16 + ldmatrix.x4, fp32 accum.
// 3-stage cp.async pipeline, one __syncthreads per tile. 2 CTAs/SM.
// ---------------------------------------------------------------------------
struct SegH {
    const __half* A;
    const __half* B;
    const float*  bias;
    float*        C;
    __half*       Ch;
    int lda, ldb, ldc, K, xStart;
};
struct SegHParams { SegH seg[12]; };

#define HT_ROWS 128
#define HT_LDS  72
#define HT_TILE (HT_ROWS * HT_LDS)
#define N_STAGE 3

__global__ void __launch_bounds__(256, 2) gemm_tn_f16(SegHParams p)
{
    extern __shared__ __half smemH[];
    __half* Asb = smemH;
    __half* Bsb = smemH + N_STAGE * HT_TILE;

    const int bx = blockIdx.x;
    int si = 0;
    #pragma unroll
    for (int i = 1; i < 12; i++)
        if (bx >= p.seg[i].xStart) si = i;
    const SegH d = p.seg[si];

    const int bn = (bx - d.xStart) * 128;
    const int bm = blockIdx.y * 128;
    const int tid  = threadIdx.x;
    const int warp = tid >> 5, lane = tid & 31;
    const int wm = (warp & 1) * 64;
    const int wn = (warp >> 1) * 32;
    const int g = lane >> 2, t = lane & 3;

    float acc[4][4][4];
    #pragma unroll
    for (int i = 0; i < 4; i++)
        #pragma unroll
        for (int j = 0; j < 4; j++)
            #pragma unroll
            for (int r = 0; r < 4; r++) acc[i][j][r] = 0.f;

    const int T = d.K >> 6;

    const uint32_t AsU = (uint32_t)__cvta_generic_to_shared(Asb);
    const uint32_t BsU = (uint32_t)__cvta_generic_to_shared(Bsb);
    const int a_row = (lane & 15);
    const int a_col = (lane >> 4) << 3;
    const int b_row = (lane & 7) + ((lane >> 4) << 3);
    const int b_col = (lane & 8);
    uint32_t a_base[4], b_base[2];
    #pragma unroll
    for (int i = 0; i < 4; i++)
        a_base[i] = AsU + ((wm + i * 16 + a_row) * HT_LDS + a_col) * 2;
    #pragma unroll
    for (int q = 0; q < 2; q++)
        b_base[q] = BsU + ((wn + q * 16 + b_row) * HT_LDS + b_col) * 2;

    auto issue = [&](int ti) {
        const int buf = ti % N_STAGE;
        const int kt = ti * 64;
        __half* As = Asb + buf * HT_TILE;
        __half* Bs = Bsb + buf * HT_TILE;
        #pragma unroll
        for (int i = 0; i < 4; i++) {
            const int idx = tid + i * 256;
            const int r = idx >> 3, c = idx & 7;
            cp16(&As[r * HT_LDS + c * 8],
                 d.A + (size_t)(bm + r) * d.lda + kt + c * 8);
        }
        #pragma unroll
        for (int i = 0; i < 4; i++) {
            const int idx = tid + i * 256;
            const int r = idx >> 3, c = idx & 7;
            cp16(&Bs[r * HT_LDS + c * 8],
                 d.B + (size_t)(bn + r) * d.ldb + kt + c * 8);
        }
        asm volatile("cp.async.commit_group;\n");
    };

    issue(0);
    if (T > 1) issue(1);

    for (int ti = 0; ti < T; ti++) {
        if (ti + 2 <= T) asm volatile("cp.async.wait_group 1;\n");
        else             asm volatile("cp.async.wait_group 0;\n");
        __syncthreads();

        if (ti + 2 < T) issue(ti + 2);

        const uint32_t bufOff = (uint32_t)(ti % N_STAGE) * (HT_TILE * 2);
        #pragma unroll
        for (int ks = 0; ks < 4; ks++) {
            const uint32_t kOff = bufOff + ks * 32;
            unsigned af[4][4], bf[4][2];
            #pragma unroll
            for (int i = 0; i < 4; i++)
                ldm_x4(af[i][0], af[i][1], af[i][2], af[i][3], a_base[i] + kOff);
            #pragma unroll
            for (int q = 0; q < 2; q++)
                ldm_x4(bf[2 * q][0], bf[2 * q][1], bf[2 * q + 1][0], bf[2 * q + 1][1],
                       b_base[q] + kOff);
            #pragma unroll
            for (int i = 0; i < 4; i++)
                #pragma unroll
                for (int j = 0; j < 4; j++)
                    asm volatile(
                        "mma.sync.aligned.m16n8k16.row.col.f32.f16.f16.f32 "
                        "{%0,%1,%2,%3},{%4,%5,%6,%7},{%8,%9},{%0,%1,%2,%3};\n"
                        : "+f"(acc[i][j][0]), "+f"(acc[i][j][1]),
                          "+f"(acc[i][j][2]), "+f"(acc[i][j][3])
                        : "r"(af[i][0]), "r"(af[i][1]), "r"(af[i][2]), "r"(af[i][3]),
                          "r"(bf[j][0]), "r"(bf[j][1]));
        }
    }

    #pragma unroll
    for (int i = 0; i < 4; i++) {
        #pragma unroll
        for (int j = 0; j < 4; j++) {
            const int row = bm + wm + i * 16 + g;
            const int col = bn + wn + j * 8 + t * 2;
            float b0 = 0.f, b1 = 0.f;
            if (d.bias) { b0 = d.bias[col]; b1 = d.bias[col + 1]; }
            const float v00 = acc[i][j][0] + b0, v01 = acc[i][j][1] + b1;
            const float v10 = acc[i][j][2] + b0, v11 = acc[i][j][3] + b1;
            if (d.Ch) {
                *(__half2*)(d.Ch + (size_t)row * d.ldc + col) = __floats2half2_rn(v00, v01);
                *(__half2*)(d.Ch + (size_t)(row + 8) * d.ldc + col) = __floats2half2_rn(v10, v11);
            } else {
                *(float2*)(d.C + (size_t)row * d.ldc + col) = make_float2(v00, v01);
                *(float2*)(d.C + (size_t)(row + 8) * d.ldc + col) = make_float2(v10, v11);
            }
        }
    }
}

// ---------------------------------------------------------------------------
// Fused biases
// ---------------------------------------------------------------------------
__global__ void __launch_bounds__(256) fbias_kernel(
    const float* __restrict__ Wk, const float* __restrict__ bk,
    const float* __restrict__ Wv, const float* __restrict__ bv,
    const float* __restrict__ bs, const float* __restrict__ semb)
{
    const int gw   = blockIdx.x * 8 + (threadIdx.x >> 5);
    const int lane = threadIdx.x & 31;
    const int which = gw / (SS * FD);
    const int rem   = gw - which * (SS * FD);
    const int i = rem >> 10;
    const int f = rem & 1023;
    const float* W = which ? Wv : Wk;
    const float* Wr  = W + (size_t)f * FD;
    const float* bsr = bs + i * FD;
    const float* ser = semb + i * FD;
    float sum = 0.f;
    for (int j = lane; j < FD; j += 32) sum += Wr[j] * (bsr[j] + ser[j]);
    sum = wredsum(sum);
    if (lane == 0) {
        if (which) g_fbv[rem] = sum + bv[f];
        else       g_fbk[rem] = sum + bk[f];
    }
}

// ---------------------------------------------------------------------------
// FUSED: attention + scale importance + gate + softmax + combine
// ---------------------------------------------------------------------------
__global__ void __launch_bounds__(256) fused_tail_kernel(
    const int* __restrict__ routes, const float* __restrict__ tptr,
    const float* __restrict__ gamma, const float* __restrict__ beta,
    const float* __restrict__ Wg2, const float* __restrict__ bg2,
    const float* __restrict__ l0, const float* __restrict__ l1,
    const float* __restrict__ l2, const float* __restrict__ l3,
    const float* __restrict__ l4, float* __restrict__ out)
{
    const int b = blockIdx.x;
    __shared__ float Qs[FD];
    __shared__ __half Ks[SS * FD];
    __shared__ __half Vs[SS * FD];
    __shared__ float hs[GD];
    __shared__ float ssi[SS];
    __shared__ float aws[SS];
    __shared__ int   rts[SS * LW];
    __shared__ float rbuf[64];
    const int tid = threadIdx.x;
    const int warp = tid >> 5, lane = tid & 31;

    ((float4*)Qs)[tid] = ((const float4*)(g_Q + (size_t)b * FD))[tid];
    const uint4* k4 = (const uint4*)(g_Kh + (size_t)b * SS * FD);
    const uint4* v4 = (const uint4*)(g_Vh + (size_t)b * SS * FD);
    #pragma unroll
    for (int i = 0; i < 3; i++) {
        const int idx = tid + 256 * i;
        if (idx < 640) {
            ((uint4*)Ks)[idx] = k4[idx];
            ((uint4*)Vs)[idx] = v4[idx];
        }
    }
    if (tid < SS * LW) rts[tid] = routes[tid];
    if (tid < SS) ssi[tid] = 0.f;
    const float2 hv = ((const float2*)(g_H + (size_t)b * GD))[tid];
    __syncthreads();

    const float sc_mul = 1.0f / (8.0f * fabsf(*tptr));
    for (int p = warp; p < HH * SS; p += 8) {
        const int h = p / SS, s = p - (p / SS) * SS;
        const float q0 = Qs[h * DD + lane];
        const float q1 = Qs[h * DD + 32 + lane];
        float scw[LW]; int jr[LW];
        #pragma unroll
        for (int w = 0; w < LW; w++) {
            const int j = rts[s * LW + w];
            jr[w] = j;
            const __half* kh = Ks + j * FD + h * DD;
            float d = q0 * __half2float(kh[lane]) + q1 * __half2float(kh[lane + 32]);
            d = wredsum(d);
            scw[w] = d * sc_mul;
        }
        const float m = fmaxf(scw[0], fmaxf(scw[1], scw[2]));
        float e0 = expf(scw[0] - m), e1 = expf(scw[1] - m), e2 = expf(scw[2] - m);
        const float inv = 1.0f / (e0 + e1 + e2);
        e0 *= inv; e1 *= inv; e2 *= inv;
        float o0 = 0.f, o1 = 0.f;
        {
            const __half* vh = Vs + jr[0] * FD + h * DD;
            o0 += e0 * __half2float(vh[lane]); o1 += e0 * __half2float(vh[lane + 32]);
        }
        {
            const __half* vh = Vs + jr[1] * FD + h * DD;
            o0 += e1 * __half2float(vh[lane]); o1 += e1 * __half2float(vh[lane + 32]);
        }
        {
            const __half* vh = Vs + jr[2] * FD + h * DD;
            o0 += e2 * __half2float(vh[lane]); o1 += e2 * __half2float(vh[lane + 32]);
        }
        float n2 = o0 * o0 + o1 * o1;
        n2 = wredsum(n2);
        if (lane == 0) atomicAdd(&ssi[s], sqrtf(n2));
    }

    {
        float s1 = hv.x + hv.y;
        float s2 = hv.x * hv.x + hv.y * hv.y;
        s1 = wredsum(s1); s2 = wredsum(s2);
        if (lane == 0) { rbuf[warp] = s1; rbuf[8 + warp] = s2; }
    }
    __syncthreads();
    {
        float su = 0.f, sq = 0.f;
        #pragma unroll
        for (int w = 0; w < 8; w++) { su += rbuf[w]; sq += rbuf[8 + w]; }
        const float mu  = su * (1.0f / GD);
        const float ex2 = sq * (1.0f / GD);
        const float rstd = rsqrtf(ex2 - mu * mu + 1e-5f);

        const float2 ga = ((const float2*)gamma)[tid];
        const float2 be = ((const float2*)beta)[tid];
        float x0 = (hv.x - mu) * rstd * ga.x + be.x;
        float x1 = (hv.y - mu) * rstd * ga.y + be.y;
        hs[2 * tid + 0] = 0.5f * x0 * (1.f + erff(x0 * 0.70710678118f));
        hs[2 * tid + 1] = 0.5f * x1 * (1.f + erff(x1 * 0.70710678118f));
    }
    __syncthreads();

    {
        const float xa = hs[tid];
        const float xb = hs[tid + 256];
        float p[SS];
        #pragma unroll
        for (int s = 0; s < SS; s++)
            p[s] = xa * Wg2[s * GD + tid] + xb * Wg2[s * GD + tid + 256];
        #pragma unroll
        for (int s = 0; s < SS; s++) p[s] = wredsum(p[s]);
        if (lane == 0)
            #pragma unroll
            for (int s = 0; s < SS; s++) rbuf[16 + warp * SS + s] = p[s];
    }
    __syncthreads();

    if (tid == 0) {
        float cs[SS];
        #pragma unroll
        for (int s = 0; s < SS; s++) {
            float gl = bg2[s];
            #pragma unroll
            for (int w = 0; w < 8; w++) gl += rbuf[16 + w * SS + s];
            cs[s] = 0.7f * (ssi[s] * (1.0f / (float)HH)) + 0.3f * gl;
        }
        float m = cs[0];
        #pragma unroll
        for (int s = 1; s < SS; s++) m = fmaxf(m, cs[s]);
        float e[SS], tot = 0.f;
        #pragma unroll
        for (int s = 0; s < SS; s++) { e[s] = expf(cs[s] - m); tot += e[s]; }
        const float inv = 1.0f / tot;
        #pragma unroll
        for (int s = 0; s < SS; s++) aws[s] = e[s] * inv;
    }
    __syncthreads();

    const float w0 = aws[0], w1 = aws[1], w2 = aws[2], w3 = aws[3], w4 = aws[4];
    if (tid < SS) out[(size_t)BQ * CC + (size_t)b * SS + tid] = aws[tid];
    if (tid < CC / 4) {
        const size_t idx = (size_t)b * (CC / 4) + tid;
        const float4 a0 = ((const float4*)l0)[idx];
        const float4 a1 = ((const float4*)l1)[idx];
        const float4 a2 = ((const float4*)l2)[idx];
        const float4 a3 = ((const float4*)l3)[idx];
        const float4 a4 = ((const float4*)l4)[idx];
        float4 r;
        r.x = w0 * a0.x + w1 * a1.x + w2 * a2.x + w3 * a3.x + w4 * a4.x;
        r.y = w0 * a0.y + w1 * a1.y + w2 * a2.y + w3 * a3.y + w4 * a4.y;
        r.z = w0 * a0.z + w1 * a1.z + w2 * a2.z + w3 * a3.z + w4 * a4.z;
        r.w = w0 * a0.w + w1 * a1.w + w2 * a2.w + w3 * a3.w + w4 * a4.w;
        ((float4*)out)[idx] = r;
    }
}

// ---------------------------------------------------------------------------
// kernel_launch
// ---------------------------------------------------------------------------
extern "C" void kernel_launch(void* const* d_in, const int* in_sizes, int n_in,
                              void* d_out, int out_size)
{
    (void)in_sizes; (void)n_in; (void)out_size;
    const float* features = (const float*)d_in[0];
    const float* sf[SS]     = {(const float*)d_in[1],  (const float*)d_in[2],
                               (const float*)d_in[3],  (const float*)d_in[4],
                               (const float*)d_in[5]};
    const float* logits[SS] = {(const float*)d_in[6],  (const float*)d_in[7],
                               (const float*)d_in[8],  (const float*)d_in[9],
                               (const float*)d_in[10]};
    const float* Ws[SS]     = {(const float*)d_in[11], (const float*)d_in[12],
                               (const float*)d_in[13], (const float*)d_in[14],
                               (const float*)d_in[15]};
    const float* bs   = (const float*)d_in[16];
    const float* semb = (const float*)d_in[17];
    const float* Wq   = (const float*)d_in[18];
    const float* bq   = (const float*)d_in[19];
    const float* Wk   = (const float*)d_in[20];
    const float* bk   = (const float*)d_in[21];
    const float* Wv   = (const float*)d_in[22];
    const float* bv   = (const float*)d_in[23];
    const float* Wg1  = (const float*)d_in[24];
    const float* bg1  = (const float*)d_in[25];
    const float* gam  = (const float*)d_in[26];
    const float* bet  = (const float*)d_in[27];
    const float* Wg2  = (const float*)d_in[28];
    const float* bg2  = (const float*)d_in[29];
    const float* temp = (const float*)d_in[30];
    const int*   routes = (const int*)d_in[31];

    __half *MKp, *MVp, *WsT, *sfh, *feath, *Wqh, *Wg1h, *Wkh, *Wvh, *Kbh, *Vbh;
    float *fbk, *fbv, *Qb, *Hb;
    cudaGetSymbolAddress((void**)&MKp,   g_MKp);
    cudaGetSymbolAddress((void**)&MVp,   g_MVp);
    cudaGetSymbolAddress((void**)&WsT,   g_WsT);
    cudaGetSymbolAddress((void**)&sfh,   g_sfh);
    cudaGetSymbolAddress((void**)&feath, g_feath);
    cudaGetSymbolAddress((void**)&Wqh,   g_Wqh);
    cudaGetSymbolAddress((void**)&Wg1h,  g_Wg1h);
    cudaGetSymbolAddress((void**)&Wkh,   g_Wkh);
    cudaGetSymbolAddress((void**)&Wvh,   g_Wvh);
    cudaGetSymbolAddress((void**)&Kbh, g_Kh);
    cudaGetSymbolAddress((void**)&Vbh, g_Vh);
    cudaGetSymbolAddress((void**)&fbk, g_fbk);
    cudaGetSymbolAddress((void**)&fbv, g_fbv);
    cudaGetSymbolAddress((void**)&Qb,  g_Q);
    cudaGetSymbolAddress((void**)&Hb,  g_H);

    static const int SC[SS]   = {64, 128, 256, 512, 1024};
    static const int OFF[SS]  = {0, 64, 192, 448, 960};        // sf concat (unpadded)
    static const int PAD[SS]  = {128, 128, 256, 512, 1024};    // padded N per segment
    static const int POFF[SS] = {0, 128, 256, 512, 1024};      // padded offsets

    // ---- 0) Convert fp32 -> fp16 operands (10 segments) ----
    {
        ConvParams cp{};
        for (int i = 0; i < SS; i++)
            cp.seg[i] = {sf[i], sfh + (size_t)BQ * OFF[i], (BQ * SC[i]) / 4};
        cp.seg[5] = {features, feath, (BQ * FD) / 4};
        cp.seg[6] = {Wq,  Wqh,  (FD * FD) / 4};
        cp.seg[7] = {Wg1, Wg1h, (GD * FD) / 4};
        cp.seg[8] = {Wk,  Wkh,  (FD * FD) / 4};
        cp.seg[9] = {Wv,  Wvh,  (FD * FD) / 4};
        convert_kernel<<<1184, 256>>>(cp);
    }

    // ---- 0b) Transpose Ws -> WsT (padded, half) ----
    {
        TParams tp{};
        int x = 0;
        for (int i = 0; i < SS; i++) {
            tp.seg[i] = {Ws[i], WsT + (size_t)POFF[i] * FD, SC[i], x};
            x += 32 * (PAD[i] / 32);
        }
        transpose_kernel<<<x, 256>>>(tp);
    }

    // ---- 1) Fused biases ----
    fbias_kernel<<<(2 * SS * FD) / 8, 256>>>(Wk, bk, Wv, bv, bs, semb);

    const int smemBytes = 2 * N_STAGE * HT_TILE * sizeof(__half);  // 110592
    cudaFuncSetAttribute(gemm_tn_f16,
                         cudaFuncAttributeMaxDynamicSharedMemorySize, smemBytes);

    // ---- 2) Prep GEMM on the fast f16 path: MK = Wk @ Ws, MV = Wv @ Ws ----
    {
        SegHParams p{};
        for (int i = 0; i < 12; i++) p.seg[i].xStart = 0x7FFFFFFF;
        int x = 0;
        for (int i = 0; i < SS; i++) {
            p.seg[i] = {Wkh, WsT + (size_t)POFF[i] * FD, nullptr,
                        nullptr, MKp + POFF[i], FD, FD, PSUM, FD, x};
            x += PAD[i] / 128;
        }
        for (int i = 0; i < SS; i++) {
            p.seg[5 + i] = {Wvh, WsT + (size_t)POFF[i] * FD, nullptr,
                            nullptr, MVp + POFF[i], FD, FD, PSUM, FD, x};
            x += PAD[i] / 128;
        }
        gemm_tn_f16<<<dim3(x, FD / 128), 256, smemBytes>>>(p);
    }

    // ---- 3) Main batched TN fp16 GEMM: K x5, V x5, Q, H ----
    {
        SegHParams p{};
        int x = 0;
        for (int i = 0; i < SS; i++) {
            p.seg[i] = {sfh + (size_t)BQ * OFF[i], MKp + POFF[i], fbk + i * FD,
                        nullptr, Kbh + i * FD, SC[i], PSUM, SS * FD, SC[i], x};
            x += FD / 128;
        }
        for (int i = 0; i < SS; i++) {
            p.seg[5 + i] = {sfh + (size_t)BQ * OFF[i], MVp + POFF[i], fbv + i * FD,
                            nullptr, Vbh + i * FD, SC[i], PSUM, SS * FD, SC[i], x};
            x += FD / 128;
        }
        p.seg[10] = {feath, Wqh,  bq,  Qb, nullptr, FD, FD, FD, FD, x};
        x += FD / 128;
        p.seg[11] = {feath, Wg1h, bg1, Hb, nullptr, FD, FD, GD, FD, x};
        x += GD / 128;

        gemm_tn_f16<<<dim3(x, BQ / 128), 256, smemBytes>>>(p);
    }

    // ---- 4) Fused tail ----
    fused_tail_kernel<<<BQ, 256>>>(routes, temp, gam, bet, Wg2, bg2,
                                   logits[0], logits[1], logits[2],
                                   logits[3], logits[4], (float*)d_out);
}

// round 14
// speedup vs baseline: 1.2440x; 1.0190x over previous
#include <cuda_runtime.h>
#include <cuda_fp16.h>
#include <cstdint>

#define BQ    8192
#define FD    1024
#define HH    16
#define DD    64
#define SS    5
#define LW    3
#define CC    1000
#define GD    512
#define CSUM  1984   // 64+128+256+512+1024
#define PSUM  2048   // padded: 128+128+256+512+1024

// ---------------------------------------------------------------------------
// Scratch
// ---------------------------------------------------------------------------
__device__ __half g_MKp[(size_t)FD * PSUM];
__device__ __half g_MVp[(size_t)FD * PSUM];
__device__ __half g_WsT[(size_t)PSUM * FD];
__device__ __half g_sfh[(size_t)BQ * CSUM];
__device__ __half g_feath[(size_t)BQ * FD];
__device__ __half g_Wqh[FD * FD];
__device__ __half g_Wg1h[GD * FD];
__device__ __half g_Wkh[FD * FD];
__device__ __half g_Wvh[FD * FD];
__device__ float g_fbk[SS * FD];
__device__ float g_fbv[SS * FD];
__device__ __half g_Kh[(size_t)BQ * SS * FD];
__device__ __half g_Vh[(size_t)BQ * SS * FD];
__device__ float g_Q[(size_t)BQ * FD];
__device__ float g_H[(size_t)BQ * GD];

// ---------------------------------------------------------------------------
// Helpers
// ---------------------------------------------------------------------------
__device__ __forceinline__ float wredsum(float v) {
    #pragma unroll
    for (int o = 16; o; o >>= 1) v += __shfl_xor_sync(0xffffffffu, v, o);
    return v;
}
__device__ __forceinline__ void cp16(void* s, const void* g) {
    uint32_t sa = (uint32_t)__cvta_generic_to_shared(s);
    asm volatile("cp.async.cg.shared.global [%0], [%1], 16;\n" :: "r"(sa), "l"(g));
}
__device__ __forceinline__ void ldm_x4(unsigned& r0, unsigned& r1, unsigned& r2, unsigned& r3,
                                       uint32_t addr) {
    asm volatile("ldmatrix.sync.aligned.m8n8.x4.shared.b16 {%0,%1,%2,%3}, [%4];"
                 : "=r"(r0), "=r"(r1), "=r"(r2), "=r"(r3) : "r"(addr));
}

// ---------------------------------------------------------------------------
// f32 -> f16 conversion (10 segments, grid-stride)
// ---------------------------------------------------------------------------
struct ConvSeg { const float* src; __half* dst; int n4; };
struct ConvParams { ConvSeg seg[10]; };

__global__ void __launch_bounds__(256) convert_kernel(ConvParams p)
{
    const int stride = gridDim.x * blockDim.x;
    const int t0 = blockIdx.x * blockDim.x + threadIdx.x;
    #pragma unroll
    for (int s = 0; s < 10; s++) {
        const float* src = p.seg[s].src;
        __half* dst = p.seg[s].dst;
        const int n4 = p.seg[s].n4;
        for (int i = t0; i < n4; i += stride) {
            const float4 v = ((const float4*)src)[i];
            ((__half2*)dst)[2 * i + 0] = __floats2half2_rn(v.x, v.y);
            ((__half2*)dst)[2 * i + 1] = __floats2half2_rn(v.z, v.w);
        }
    }
}

// ---------------------------------------------------------------------------
// Transpose Ws_i [FD, sc] f32 -> WsT [P, FD] half (rows >= sc zero-filled)
// ---------------------------------------------------------------------------
struct TSeg { const float* src; __half* dst; int sc; int xStart; };
struct TParams { TSeg seg[SS]; };

__global__ void __launch_bounds__(256) transpose_kernel(TParams p)
{
    const int bx = blockIdx.x;
    int si = 0;
    #pragma unroll
    for (int i = 1; i < SS; i++)
        if (bx >= p.seg[i].xStart) si = i;
    const TSeg d = p.seg[si];

    const int local = bx - d.xStart;
    const int jt = local & 31;
    const int nt = local >> 5;
    const int tx = threadIdx.x & 31, ty = threadIdx.x >> 5;

    __shared__ float tile[32][33];
    const int n_in = nt * 32 + tx;
    #pragma unroll
    for (int r = 0; r < 4; r++) {
        const int j = jt * 32 + ty + r * 8;
        tile[ty + r * 8][tx] = (n_in < d.sc) ? d.src[(size_t)j * d.sc + n_in] : 0.f;
    }
    __syncthreads();
    const int j_out = jt * 32 + tx;
    #pragma unroll
    for (int r = 0; r < 4; r++) {
        const int n = nt * 32 + ty + r * 8;
        d.dst[(size_t)n * FD + j_out] = __float2half(tile[tx][ty + r * 8]);
    }
}

// ---------------------------------------------------------------------------
// Batched TN GEMM, fp16 m16n8k16 + ldmatrix.x4, fp32 accum.
// 3-stage cp.async pipeline, one __syncthreads per tile. 2 CTAs/SM.
// ---------------------------------------------------------------------------
struct SegH {
    const __half* A;
    const __half* B;
    const float*  bias;
    float*        C;
    __half*       Ch;
    int lda, ldb, ldc, K, xStart;
};
struct SegHParams { SegH seg[12]; };

#define HT_ROWS 128
#define HT_LDS  72
#define HT_TILE (HT_ROWS * HT_LDS)
#define N_STAGE 3

__global__ void __launch_bounds__(256, 2) gemm_tn_f16(SegHParams p)
{
    extern __shared__ __half smemH[];
    __half* Asb = smemH;
    __half* Bsb = smemH + N_STAGE * HT_TILE;

    const int bx = blockIdx.x;
    int si = 0;
    #pragma unroll
    for (int i = 1; i < 12; i++)
        if (bx >= p.seg[i].xStart) si = i;
    const SegH d = p.seg[si];

    const int bn = (bx - d.xStart) * 128;
    const int bm = blockIdx.y * 128;
    const int tid  = threadIdx.x;
    const int warp = tid >> 5, lane = tid & 31;
    const int wm = (warp & 1) * 64;
    const int wn = (warp >> 1) * 32;
    const int g = lane >> 2, t = lane & 3;

    float acc[4][4][4];
    #pragma unroll
    for (int i = 0; i < 4; i++)
        #pragma unroll
        for (int j = 0; j < 4; j++)
            #pragma unroll
            for (int r = 0; r < 4; r++) acc[i][j][r] = 0.f;

    const int T = d.K >> 6;

    const uint32_t AsU = (uint32_t)__cvta_generic_to_shared(Asb);
    const uint32_t BsU = (uint32_t)__cvta_generic_to_shared(Bsb);
    const int a_row = (lane & 15);
    const int a_col = (lane >> 4) << 3;
    const int b_row = (lane & 7) + ((lane >> 4) << 3);
    const int b_col = (lane & 8);
    uint32_t a_base[4], b_base[2];
    #pragma unroll
    for (int i = 0; i < 4; i++)
        a_base[i] = AsU + ((wm + i * 16 + a_row) * HT_LDS + a_col) * 2;
    #pragma unroll
    for (int q = 0; q < 2; q++)
        b_base[q] = BsU + ((wn + q * 16 + b_row) * HT_LDS + b_col) * 2;

    auto issue = [&](int ti) {
        const int buf = ti % N_STAGE;
        const int kt = ti * 64;
        __half* As = Asb + buf * HT_TILE;
        __half* Bs = Bsb + buf * HT_TILE;
        #pragma unroll
        for (int i = 0; i < 4; i++) {
            const int idx = tid + i * 256;
            const int r = idx >> 3, c = idx & 7;
            cp16(&As[r * HT_LDS + c * 8],
                 d.A + (size_t)(bm + r) * d.lda + kt + c * 8);
        }
        #pragma unroll
        for (int i = 0; i < 4; i++) {
            const int idx = tid + i * 256;
            const int r = idx >> 3, c = idx & 7;
            cp16(&Bs[r * HT_LDS + c * 8],
                 d.B + (size_t)(bn + r) * d.ldb + kt + c * 8);
        }
        asm volatile("cp.async.commit_group;\n");
    };

    issue(0);
    if (T > 1) issue(1);

    for (int ti = 0; ti < T; ti++) {
        if (ti + 2 <= T) asm volatile("cp.async.wait_group 1;\n");
        else             asm volatile("cp.async.wait_group 0;\n");
        __syncthreads();

        if (ti + 2 < T) issue(ti + 2);

        const uint32_t bufOff = (uint32_t)(ti % N_STAGE) * (HT_TILE * 2);
        #pragma unroll
        for (int ks = 0; ks < 4; ks++) {
            const uint32_t kOff = bufOff + ks * 32;
            unsigned af[4][4], bf[4][2];
            #pragma unroll
            for (int i = 0; i < 4; i++)
                ldm_x4(af[i][0], af[i][1], af[i][2], af[i][3], a_base[i] + kOff);
            #pragma unroll
            for (int q = 0; q < 2; q++)
                ldm_x4(bf[2 * q][0], bf[2 * q][1], bf[2 * q + 1][0], bf[2 * q + 1][1],
                       b_base[q] + kOff);
            #pragma unroll
            for (int i = 0; i < 4; i++)
                #pragma unroll
                for (int j = 0; j < 4; j++)
                    asm volatile(
                        "mma.sync.aligned.m16n8k16.row.col.f32.f16.f16.f32 "
                        "{%0,%1,%2,%3},{%4,%5,%6,%7},{%8,%9},{%0,%1,%2,%3};\n"
                        : "+f"(acc[i][j][0]), "+f"(acc[i][j][1]),
                          "+f"(acc[i][j][2]), "+f"(acc[i][j][3])
                        : "r"(af[i][0]), "r"(af[i][1]), "r"(af[i][2]), "r"(af[i][3]),
                          "r"(bf[j][0]), "r"(bf[j][1]));
        }
    }

    #pragma unroll
    for (int i = 0; i < 4; i++) {
        #pragma unroll
        for (int j = 0; j < 4; j++) {
            const int row = bm + wm + i * 16 + g;
            const int col = bn + wn + j * 8 + t * 2;
            float b0 = 0.f, b1 = 0.f;
            if (d.bias) { b0 = d.bias[col]; b1 = d.bias[col + 1]; }
            const float v00 = acc[i][j][0] + b0, v01 = acc[i][j][1] + b1;
            const float v10 = acc[i][j][2] + b0, v11 = acc[i][j][3] + b1;
            if (d.Ch) {
                *(__half2*)(d.Ch + (size_t)row * d.ldc + col) = __floats2half2_rn(v00, v01);
                *(__half2*)(d.Ch + (size_t)(row + 8) * d.ldc + col) = __floats2half2_rn(v10, v11);
            } else {
                *(float2*)(d.C + (size_t)row * d.ldc + col) = make_float2(v00, v01);
                *(float2*)(d.C + (size_t)(row + 8) * d.ldc + col) = make_float2(v10, v11);
            }
        }
    }
}

// ---------------------------------------------------------------------------
// Fused biases
// ---------------------------------------------------------------------------
__global__ void __launch_bounds__(256) fbias_kernel(
    const float* __restrict__ Wk, const float* __restrict__ bk,
    const float* __restrict__ Wv, const float* __restrict__ bv,
    const float* __restrict__ bs, const float* __restrict__ semb)
{
    const int gw   = blockIdx.x * 8 + (threadIdx.x >> 5);
    const int lane = threadIdx.x & 31;
    const int which = gw / (SS * FD);
    const int rem   = gw - which * (SS * FD);
    const int i = rem >> 10;
    const int f = rem & 1023;
    const float* W = which ? Wv : Wk;
    const float* Wr  = W + (size_t)f * FD;
    const float* bsr = bs + i * FD;
    const float* ser = semb + i * FD;
    float sum = 0.f;
    for (int j = lane; j < FD; j += 32) sum += Wr[j] * (bsr[j] + ser[j]);
    sum = wredsum(sum);
    if (lane == 0) {
        if (which) g_fbv[rem] = sum + bv[f];
        else       g_fbk[rem] = sum + bk[f];
    }
}

// ---------------------------------------------------------------------------
// FUSED tail: attention + scale importance + gate + softmax + combine
// cp.async staging for Q/K/V; LN stats overlapped with the loads.
// ---------------------------------------------------------------------------
__global__ void __launch_bounds__(256) fused_tail_kernel(
    const int* __restrict__ routes, const float* __restrict__ tptr,
    const float* __restrict__ gamma, const float* __restrict__ beta,
    const float* __restrict__ Wg2, const float* __restrict__ bg2,
    const float* __restrict__ l0, const float* __restrict__ l1,
    const float* __restrict__ l2, const float* __restrict__ l3,
    const float* __restrict__ l4, float* __restrict__ out)
{
    const int b = blockIdx.x;
    __shared__ float Qs[FD];
    __shared__ __half Ks[SS * FD];
    __shared__ __half Vs[SS * FD];
    __shared__ float hs[GD];
    __shared__ float ssi[SS];
    __shared__ float aws[SS];
    __shared__ int   rts[SS * LW];
    __shared__ float rbuf[64];
    const int tid = threadIdx.x;
    const int warp = tid >> 5, lane = tid & 31;

    // ---- issue async staging of Q (4KB) + K/V (10KB each) ----
    cp16(&Qs[tid * 4], g_Q + (size_t)b * FD + tid * 4);
    {
        const __half* kg = g_Kh + (size_t)b * SS * FD;
        const __half* vg = g_Vh + (size_t)b * SS * FD;
        #pragma unroll
        for (int i = 0; i < 3; i++) {
            const int idx = tid + 256 * i;
            if (idx < 640) {
                cp16(&Ks[idx * 8], kg + idx * 8);
                cp16(&Vs[idx * 8], vg + idx * 8);
            }
        }
    }
    asm volatile("cp.async.commit_group;\n");

    if (tid < SS * LW) rts[tid] = routes[tid];
    if (tid < SS) ssi[tid] = 0.f;

    // ---- overlap: gate LN statistics (register-only) ----
    const float2 hv = ((const float2*)(g_H + (size_t)b * GD))[tid];
    {
        float s1 = hv.x + hv.y;
        float s2 = hv.x * hv.x + hv.y * hv.y;
        s1 = wredsum(s1); s2 = wredsum(s2);
        if (lane == 0) { rbuf[warp] = s1; rbuf[8 + warp] = s2; }
    }

    asm volatile("cp.async.wait_group 0;\n");
    __syncthreads();

    // ---- Phase A: attention + scale importance ----
    const float sc_mul = 1.0f / (8.0f * fabsf(*tptr));
    for (int p = warp; p < HH * SS; p += 8) {
        const int h = p / SS, s = p - (p / SS) * SS;
        const float q0 = Qs[h * DD + lane];
        const float q1 = Qs[h * DD + 32 + lane];
        float scw[LW]; int jr[LW];
        #pragma unroll
        for (int w = 0; w < LW; w++) {
            const int j = rts[s * LW + w];
            jr[w] = j;
            const __half* kh = Ks + j * FD + h * DD;
            float d = q0 * __half2float(kh[lane]) + q1 * __half2float(kh[lane + 32]);
            d = wredsum(d);
            scw[w] = d * sc_mul;
        }
        const float m = fmaxf(scw[0], fmaxf(scw[1], scw[2]));
        float e0 = expf(scw[0] - m), e1 = expf(scw[1] - m), e2 = expf(scw[2] - m);
        const float inv = 1.0f / (e0 + e1 + e2);
        e0 *= inv; e1 *= inv; e2 *= inv;
        float o0 = 0.f, o1 = 0.f;
        {
            const __half* vh = Vs + jr[0] * FD + h * DD;
            o0 += e0 * __half2float(vh[lane]); o1 += e0 * __half2float(vh[lane + 32]);
        }
        {
            const __half* vh = Vs + jr[1] * FD + h * DD;
            o0 += e1 * __half2float(vh[lane]); o1 += e1 * __half2float(vh[lane + 32]);
        }
        {
            const __half* vh = Vs + jr[2] * FD + h * DD;
            o0 += e2 * __half2float(vh[lane]); o1 += e2 * __half2float(vh[lane + 32]);
        }
        float n2 = o0 * o0 + o1 * o1;
        n2 = wredsum(n2);
        if (lane == 0) atomicAdd(&ssi[s], sqrtf(n2));
    }

    // ---- LN normalize + GELU (rbuf visible since the barrier) ----
    {
        float su = 0.f, sq = 0.f;
        #pragma unroll
        for (int w = 0; w < 8; w++) { su += rbuf[w]; sq += rbuf[8 + w]; }
        const float mu  = su * (1.0f / GD);
        const float ex2 = sq * (1.0f / GD);
        const float rstd = rsqrtf(ex2 - mu * mu + 1e-5f);

        const float2 ga = ((const float2*)gamma)[tid];
        const float2 be = ((const float2*)beta)[tid];
        float x0 = (hv.x - mu) * rstd * ga.x + be.x;
        float x1 = (hv.y - mu) * rstd * ga.y + be.y;
        hs[2 * tid + 0] = 0.5f * x0 * (1.f + erff(x0 * 0.70710678118f));
        hs[2 * tid + 1] = 0.5f * x1 * (1.f + erff(x1 * 0.70710678118f));
    }
    __syncthreads();   // closes Phase A atomics + hs writes

    // ---- gate logits ----
    {
        const float xa = hs[tid];
        const float xb = hs[tid + 256];
        float p[SS];
        #pragma unroll
        for (int s = 0; s < SS; s++)
            p[s] = xa * Wg2[s * GD + tid] + xb * Wg2[s * GD + tid + 256];
        #pragma unroll
        for (int s = 0; s < SS; s++) p[s] = wredsum(p[s]);
        if (lane == 0)
            #pragma unroll
            for (int s = 0; s < SS; s++) rbuf[16 + warp * SS + s] = p[s];
    }
    __syncthreads();

    if (tid == 0) {
        float cs[SS];
        #pragma unroll
        for (int s = 0; s < SS; s++) {
            float gl = bg2[s];
            #pragma unroll
            for (int w = 0; w < 8; w++) gl += rbuf[16 + w * SS + s];
            cs[s] = 0.7f * (ssi[s] * (1.0f / (float)HH)) + 0.3f * gl;
        }
        float m = cs[0];
        #pragma unroll
        for (int s = 1; s < SS; s++) m = fmaxf(m, cs[s]);
        float e[SS], tot = 0.f;
        #pragma unroll
        for (int s = 0; s < SS; s++) { e[s] = expf(cs[s] - m); tot += e[s]; }
        const float inv = 1.0f / tot;
        #pragma unroll
        for (int s = 0; s < SS; s++) aws[s] = e[s] * inv;
    }
    __syncthreads();

    // ---- combine logits + outputs ----
    const float w0 = aws[0], w1 = aws[1], w2 = aws[2], w3 = aws[3], w4 = aws[4];
    if (tid < SS) out[(size_t)BQ * CC + (size_t)b * SS + tid] = aws[tid];
    if (tid < CC / 4) {
        const size_t idx = (size_t)b * (CC / 4) + tid;
        const float4 a0 = ((const float4*)l0)[idx];
        const float4 a1 = ((const float4*)l1)[idx];
        const float4 a2 = ((const float4*)l2)[idx];
        const float4 a3 = ((const float4*)l3)[idx];
        const float4 a4 = ((const float4*)l4)[idx];
        float4 r;
        r.x = w0 * a0.x + w1 * a1.x + w2 * a2.x + w3 * a3.x + w4 * a4.x;
        r.y = w0 * a0.y + w1 * a1.y + w2 * a2.y + w3 * a3.y + w4 * a4.y;
        r.z = w0 * a0.z + w1 * a1.z + w2 * a2.z + w3 * a3.z + w4 * a4.z;
        r.w = w0 * a0.w + w1 * a1.w + w2 * a2.w + w3 * a3.w + w4 * a4.w;
        ((float4*)out)[idx] = r;
    }
}

// ---------------------------------------------------------------------------
// kernel_launch
// ---------------------------------------------------------------------------
extern "C" void kernel_launch(void* const* d_in, const int* in_sizes, int n_in,
                              void* d_out, int out_size)
{
    (void)in_sizes; (void)n_in; (void)out_size;
    const float* features = (const float*)d_in[0];
    const float* sf[SS]     = {(const float*)d_in[1],  (const float*)d_in[2],
                               (const float*)d_in[3],  (const float*)d_in[4],
                               (const float*)d_in[5]};
    const float* logits[SS] = {(const float*)d_in[6],  (const float*)d_in[7],
                               (const float*)d_in[8],  (const float*)d_in[9],
                               (const float*)d_in[10]};
    const float* Ws[SS]     = {(const float*)d_in[11], (const float*)d_in[12],
                               (const float*)d_in[13], (const float*)d_in[14],
                               (const float*)d_in[15]};
    const float* bs   = (const float*)d_in[16];
    const float* semb = (const float*)d_in[17];
    const float* Wq   = (const float*)d_in[18];
    const float* bq   = (const float*)d_in[19];
    const float* Wk   = (const float*)d_in[20];
    const float* bk   = (const float*)d_in[21];
    const float* Wv   = (const float*)d_in[22];
    const float* bv   = (const float*)d_in[23];
    const float* Wg1  = (const float*)d_in[24];
    const float* bg1  = (const float*)d_in[25];
    const float* gam  = (const float*)d_in[26];
    const float* bet  = (const float*)d_in[27];
    const float* Wg2  = (const float*)d_in[28];
    const float* bg2  = (const float*)d_in[29];
    const float* temp = (const float*)d_in[30];
    const int*   routes = (const int*)d_in[31];

    __half *MKp, *MVp, *WsT, *sfh, *feath, *Wqh, *Wg1h, *Wkh, *Wvh, *Kbh, *Vbh;
    float *fbk, *fbv, *Qb, *Hb;
    cudaGetSymbolAddress((void**)&MKp,   g_MKp);
    cudaGetSymbolAddress((void**)&MVp,   g_MVp);
    cudaGetSymbolAddress((void**)&WsT,   g_WsT);
    cudaGetSymbolAddress((void**)&sfh,   g_sfh);
    cudaGetSymbolAddress((void**)&feath, g_feath);
    cudaGetSymbolAddress((void**)&Wqh,   g_Wqh);
    cudaGetSymbolAddress((void**)&Wg1h,  g_Wg1h);
    cudaGetSymbolAddress((void**)&Wkh,   g_Wkh);
    cudaGetSymbolAddress((void**)&Wvh,   g_Wvh);
    cudaGetSymbolAddress((void**)&Kbh, g_Kh);
    cudaGetSymbolAddress((void**)&Vbh, g_Vh);
    cudaGetSymbolAddress((void**)&fbk, g_fbk);
    cudaGetSymbolAddress((void**)&fbv, g_fbv);
    cudaGetSymbolAddress((void**)&Qb,  g_Q);
    cudaGetSymbolAddress((void**)&Hb,  g_H);

    static const int SC[SS]   = {64, 128, 256, 512, 1024};
    static const int OFF[SS]  = {0, 64, 192, 448, 960};
    static const int PAD[SS]  = {128, 128, 256, 512, 1024};
    static const int POFF[SS] = {0, 128, 256, 512, 1024};

    // ---- 0) Convert fp32 -> fp16 operands ----
    {
        ConvParams cp{};
        for (int i = 0; i < SS; i++)
            cp.seg[i] = {sf[i], sfh + (size_t)BQ * OFF[i], (BQ * SC[i]) / 4};
        cp.seg[5] = {features, feath, (BQ * FD) / 4};
        cp.seg[6] = {Wq,  Wqh,  (FD * FD) / 4};
        cp.seg[7] = {Wg1, Wg1h, (GD * FD) / 4};
        cp.seg[8] = {Wk,  Wkh,  (FD * FD) / 4};
        cp.seg[9] = {Wv,  Wvh,  (FD * FD) / 4};
        convert_kernel<<<1184, 256>>>(cp);
    }

    // ---- 0b) Transpose Ws -> WsT ----
    {
        TParams tp{};
        int x = 0;
        for (int i = 0; i < SS; i++) {
            tp.seg[i] = {Ws[i], WsT + (size_t)POFF[i] * FD, SC[i], x};
            x += 32 * (PAD[i] / 32);
        }
        transpose_kernel<<<x, 256>>>(tp);
    }

    // ---- 1) Fused biases ----
    fbias_kernel<<<(2 * SS * FD) / 8, 256>>>(Wk, bk, Wv, bv, bs, semb);

    const int smemBytes = 2 * N_STAGE * HT_TILE * sizeof(__half);  // 110592
    cudaFuncSetAttribute(gemm_tn_f16,
                         cudaFuncAttributeMaxDynamicSharedMemorySize, smemBytes);

    // ---- 2) Prep GEMM (f16 path) ----
    {
        SegHParams p{};
        for (int i = 0; i < 12; i++) p.seg[i].xStart = 0x7FFFFFFF;
        int x = 0;
        for (int i = 0; i < SS; i++) {
            p.seg[i] = {Wkh, WsT + (size_t)POFF[i] * FD, nullptr,
                        nullptr, MKp + POFF[i], FD, FD, PSUM, FD, x};
            x += PAD[i] / 128;
        }
        for (int i = 0; i < SS; i++) {
            p.seg[5 + i] = {Wvh, WsT + (size_t)POFF[i] * FD, nullptr,
                            nullptr, MVp + POFF[i], FD, FD, PSUM, FD, x};
            x += PAD[i] / 128;
        }
        gemm_tn_f16<<<dim3(x, FD / 128), 256, smemBytes>>>(p);
    }

    // ---- 3) Main batched TN fp16 GEMM ----
    {
        SegHParams p{};
        int x = 0;
        for (int i = 0; i < SS; i++) {
            p.seg[i] = {sfh + (size_t)BQ * OFF[i], MKp + POFF[i], fbk + i * FD,
                        nullptr, Kbh + i * FD, SC[i], PSUM, SS * FD, SC[i], x};
            x += FD / 128;
        }
        for (int i = 0; i < SS; i++) {
            p.seg[5 + i] = {sfh + (size_t)BQ * OFF[i], MVp + POFF[i], fbv + i * FD,
                            nullptr, Vbh + i * FD, SC[i], PSUM, SS * FD, SC[i], x};
            x += FD / 128;
        }
        p.seg[10] = {feath, Wqh,  bq,  Qb, nullptr, FD, FD, FD, FD, x};
        x += FD / 128;
        p.seg[11] = {feath, Wg1h, bg1, Hb, nullptr, FD, FD, GD, FD, x};
        x += GD / 128;

        gemm_tn_f16<<<dim3(x, BQ / 128), 256, smemBytes>>>(p);
    }

    // ---- 4) Fused tail ----
    fused_tail_kernel<<<BQ, 256>>>(routes, temp, gam, bet, Wg2, bg2,
                                   logits[0], logits[1], logits[2],
                                   logits[3], logits[4], (float*)d_out);
}